// round 10
// baseline (speedup 1.0000x reference)
#include <cuda_runtime.h>
#include <cstdint>

#define NNODES 20000
#define NEDGES 320000
#define DIM    512

// Scratch (allocation-free rule: __device__ globals)
__device__ float g_h[(size_t)NNODES * DIM];   // GEMM output h = x @ W
__device__ float g_a[(size_t)NNODES * DIM];   // layer-1 aggregation result
__device__ float g_dinv[NNODES];
__device__ int   g_deg[NNODES];
__device__ int   g_src[NEDGES];
__device__ int   g_dst[NEDGES];
__device__ int   g_is_i32;            // nonzero -> edge_index buffer is int32
__device__ int   g_rowptr[NNODES + 1];
__device__ int   g_cursor[NNODES];
__device__ int   g_csr_src[NEDGES];
__device__ float g_csr_w[NEDGES];
__device__ float g_w1t[DIM * DIM];    // W1^T, pre-converted tf32 bits
__device__ float g_w2t[DIM * DIM];    // W2^T, pre-converted tf32 bits

__device__ __forceinline__ uint32_t f2tf32(float f) {
    uint32_t r;
    asm("cvt.rna.tf32.f32 %0, %1;" : "=r"(r) : "f"(f));
    return r;
}

// ---------------------------------------------------------------------------
// Edge index normalization: detect int32 vs int64 layout, extract to int
// ---------------------------------------------------------------------------
__global__ void flag_init_kernel() { g_is_i32 = 0; }

__global__ void dtype_sniff_kernel(const int* __restrict__ ei32) {
    int i = blockIdx.x * blockDim.x + threadIdx.x;  // 0 .. E-1
    int acc = 0;
    if (i < NEDGES) acc = ei32[2 * i + 1];
#pragma unroll
    for (int o = 16; o > 0; o >>= 1) acc |= __shfl_xor_sync(0xffffffffu, acc, o);
    if ((threadIdx.x & 31) == 0 && acc != 0) atomicOr(&g_is_i32, 1);
}

__global__ void edge_convert_kernel(const void* __restrict__ ei) {
    int i = blockIdx.x * blockDim.x + threadIdx.x;  // 0 .. 2E-1
    if (i >= 2 * NEDGES) return;
    int v;
    if (g_is_i32) v = ((const int*)ei)[i];
    else          v = (int)((const long long*)ei)[i];
    if (i < NEDGES) g_src[i] = v;
    else            g_dst[i - NEDGES] = v;
}

// ---------------------------------------------------------------------------
// Degree / normalization
// ---------------------------------------------------------------------------
__global__ void deg_init_kernel() {
    int i = blockIdx.x * blockDim.x + threadIdx.x;
    if (i < NNODES) g_deg[i] = 1;  // self-loop
}

__global__ void deg_count_kernel() {
    int e = blockIdx.x * blockDim.x + threadIdx.x;
    if (e < NEDGES) atomicAdd(&g_deg[g_dst[e]], 1);
}

__global__ void dinv_kernel() {
    int i = blockIdx.x * blockDim.x + threadIdx.x;
    if (i < NNODES) g_dinv[i] = rsqrtf((float)g_deg[i]);
}

// ---------------------------------------------------------------------------
// Exclusive prefix scan of in-degree (deg-1) -> rowptr, cursor. 1 block.
// ---------------------------------------------------------------------------
#define SCAN_T 1024
__global__ void scan_kernel() {
    __shared__ int sums[SCAN_T];
    const int CH = (NNODES + SCAN_T - 1) / SCAN_T;  // 20
    int t = threadIdx.x;
    int base = t * CH;
    int local = 0;
#pragma unroll
    for (int i = 0; i < CH; i++) {
        int idx = base + i;
        if (idx < NNODES) local += g_deg[idx] - 1;
    }
    sums[t] = local;
    __syncthreads();
    for (int o = 1; o < SCAN_T; o <<= 1) {
        int v = (t >= o) ? sums[t - o] : 0;
        __syncthreads();
        sums[t] += v;
        __syncthreads();
    }
    int run = (t > 0) ? sums[t - 1] : 0;
#pragma unroll
    for (int i = 0; i < CH; i++) {
        int idx = base + i;
        if (idx < NNODES) {
            g_rowptr[idx] = run;
            g_cursor[idx] = run;
            run += g_deg[idx] - 1;
        }
    }
    if (t == SCAN_T - 1) g_rowptr[NNODES] = sums[SCAN_T - 1];
}

__global__ void scatter_kernel() {
    int e = blockIdx.x * blockDim.x + threadIdx.x;
    if (e >= NEDGES) return;
    int s = g_src[e];
    int d = g_dst[e];
    int pos = atomicAdd(&g_cursor[d], 1);
    g_csr_src[pos] = s;
    g_csr_w[pos] = g_dinv[s] * g_dinv[d];
}

// ---------------------------------------------------------------------------
// Transpose 512x512 W -> Wt with tf32 pre-conversion (RNA)
// ---------------------------------------------------------------------------
template <int WHICH>
__global__ void transpose512_kernel(const float* __restrict__ W) {
    __shared__ float t[32][33];
    int bx = blockIdx.x * 32, by = blockIdx.y * 32;
    t[threadIdx.y][threadIdx.x] = W[(by + threadIdx.y) * DIM + bx + threadIdx.x];
    __syncthreads();
    float* o = WHICH ? g_w2t : g_w1t;
    o[(bx + threadIdx.y) * DIM + by + threadIdx.x] =
        __uint_as_float(f2tf32(t[threadIdx.x][threadIdx.y]));
}

// ---------------------------------------------------------------------------
// Tensor-core GEMM via mma.sync tf32 (R6 structure, B pre-converted):
//   g_h[M,512] = op(A)[M,512] @ W[512,512]
//   MODE 0: A = Aparam (raw),     B = g_w1t (tf32 bits)
//   MODE 1: A = relu(g_a + bias), B = g_w2t (tf32 bits)
// CTA 128x128, BK=32, 256 threads = 8 warps (4 M x 2 N), warp tile 32x64.
// ---------------------------------------------------------------------------
#define SMS 36  // smem row stride (32 + 4 pad)

template <int MODE>
__global__ void __launch_bounds__(256)
mma_gemm_kernel(const float* __restrict__ Aparam, const float* __restrict__ bias) {
    __shared__ uint32_t As[128 * SMS];
    __shared__ uint32_t Bs[128 * SMS];

    const float* A  = (MODE == 0) ? Aparam : g_a;
    const float* Bt = (MODE == 0) ? g_w1t : g_w2t;

    int tid = threadIdx.x, wid = tid >> 5, lane = tid & 31;
    int row0 = blockIdx.y * 128;
    int col0 = blockIdx.x * 128;
    int wm = (wid & 3) * 32;   // warp M offset in tile
    int wn = (wid >> 2) * 64;  // warp N offset in tile
    int gq = lane >> 2;        // group id (0..7)
    int tq = lane & 3;         // thread-in-group (0..3)

    float acc[2][8][4];
#pragma unroll
    for (int mt = 0; mt < 2; mt++)
#pragma unroll
        for (int nt = 0; nt < 8; nt++)
#pragma unroll
            for (int j = 0; j < 4; j++) acc[mt][nt][j] = 0.f;

    for (int kc = 0; kc < DIM; kc += 32) {
        // ---- load A tile: 128 rows x 32 cols, 4 float4 per thread ----
#pragma unroll
        for (int i = 0; i < 4; i++) {
            int idx = tid + 256 * i;
            int r = idx >> 3, c4 = idx & 7;
            int grow = row0 + r;
            float4 v = make_float4(0.f, 0.f, 0.f, 0.f);
            if (grow < NNODES)
                v = *(const float4*)&A[(size_t)grow * DIM + kc + c4 * 4];
            if (MODE == 1) {
                float4 bb = *(const float4*)&bias[kc + c4 * 4];
                v.x = fmaxf(v.x + bb.x, 0.f);
                v.y = fmaxf(v.y + bb.y, 0.f);
                v.z = fmaxf(v.z + bb.z, 0.f);
                v.w = fmaxf(v.w + bb.w, 0.f);
            }
            uint4 tv = make_uint4(f2tf32(v.x), f2tf32(v.y), f2tf32(v.z), f2tf32(v.w));
            *(uint4*)&As[r * SMS + c4 * 4] = tv;
        }
        // ---- load B tile: rows n = col0..+127 of Wt[N][K] (already tf32 bits) ----
#pragma unroll
        for (int i = 0; i < 4; i++) {
            int idx = tid + 256 * i;
            int r = idx >> 3, c4 = idx & 7;
            float4 v = *(const float4*)&Bt[(size_t)(col0 + r) * DIM + kc + c4 * 4];
            *(uint4*)&Bs[r * SMS + c4 * 4] =
                make_uint4(__float_as_uint(v.x), __float_as_uint(v.y),
                           __float_as_uint(v.z), __float_as_uint(v.w));
        }
        __syncthreads();

#pragma unroll
        for (int ks = 0; ks < 4; ks++) {
            int k0 = ks * 8;
            uint32_t af[2][4], bf[8][2];
#pragma unroll
            for (int mt = 0; mt < 2; mt++) {
                int r = wm + mt * 16 + gq;
                af[mt][0] = As[r * SMS + k0 + tq];
                af[mt][1] = As[(r + 8) * SMS + k0 + tq];
                af[mt][2] = As[r * SMS + k0 + tq + 4];
                af[mt][3] = As[(r + 8) * SMS + k0 + tq + 4];
            }
#pragma unroll
            for (int nt = 0; nt < 8; nt++) {
                int n = wn + nt * 8 + gq;
                bf[nt][0] = Bs[n * SMS + k0 + tq];
                bf[nt][1] = Bs[n * SMS + k0 + tq + 4];
            }
#pragma unroll
            for (int mt = 0; mt < 2; mt++)
#pragma unroll
                for (int nt = 0; nt < 8; nt++) {
                    asm volatile(
                        "mma.sync.aligned.m16n8k8.row.col.f32.tf32.tf32.f32 "
                        "{%0,%1,%2,%3}, {%4,%5,%6,%7}, {%8,%9}, {%0,%1,%2,%3};"
                        : "+f"(acc[mt][nt][0]), "+f"(acc[mt][nt][1]),
                          "+f"(acc[mt][nt][2]), "+f"(acc[mt][nt][3])
                        : "r"(af[mt][0]), "r"(af[mt][1]),
                          "r"(af[mt][2]), "r"(af[mt][3]),
                          "r"(bf[nt][0]), "r"(bf[nt][1]));
                }
        }
        __syncthreads();
    }

    // ---- epilogue: fragments -> g_h ----
#pragma unroll
    for (int mt = 0; mt < 2; mt++) {
        int r0 = row0 + wm + mt * 16 + gq;
#pragma unroll
        for (int nt = 0; nt < 8; nt++) {
            int c = col0 + wn + nt * 8 + tq * 2;
            if (r0 < NNODES)
                *(float2*)&g_h[(size_t)r0 * DIM + c] =
                    make_float2(acc[mt][nt][0], acc[mt][nt][1]);
            if (r0 + 8 < NNODES)
                *(float2*)&g_h[(size_t)(r0 + 8) * DIM + c] =
                    make_float2(acc[mt][nt][2], acc[mt][nt][3]);
        }
    }
}

// ---------------------------------------------------------------------------
// Shared edge-accumulate body (fp32 exact):
//   acc = dinv[d]^2 * h[d,:] + sum_{e: dst=d} w_e * h[src_e,:]   (one float4 col)
// ---------------------------------------------------------------------------
__device__ __forceinline__ float4 agg_row(int d, int t) {
    const float4* __restrict__ h4 = (const float4*)g_h;
    float dv = g_dinv[d];
    float4 acc = h4[(size_t)d * 128 + t];
    float ws = dv * dv;
    acc.x *= ws; acc.y *= ws; acc.z *= ws; acc.w *= ws;

    int j   = g_rowptr[d];
    int end = g_rowptr[d + 1];
    for (; j + 4 <= end; j += 4) {
        int   s0 = g_csr_src[j],     s1 = g_csr_src[j + 1];
        int   s2 = g_csr_src[j + 2], s3 = g_csr_src[j + 3];
        float w0 = g_csr_w[j],       w1 = g_csr_w[j + 1];
        float w2 = g_csr_w[j + 2],   w3 = g_csr_w[j + 3];
        float4 v0 = h4[(size_t)s0 * 128 + t];
        float4 v1 = h4[(size_t)s1 * 128 + t];
        float4 v2 = h4[(size_t)s2 * 128 + t];
        float4 v3 = h4[(size_t)s3 * 128 + t];
        acc.x += v0.x * w0 + v1.x * w1 + v2.x * w2 + v3.x * w3;
        acc.y += v0.y * w0 + v1.y * w1 + v2.y * w2 + v3.y * w3;
        acc.z += v0.z * w0 + v1.z * w1 + v2.z * w2 + v3.z * w3;
        acc.w += v0.w * w0 + v1.w * w1 + v2.w * w2 + v3.w * w3;
    }
    for (; j < end; j++) {
        int   s = g_csr_src[j];
        float w = g_csr_w[j];
        float4 v = h4[(size_t)s * 128 + t];
        acc.x += v.x * w; acc.y += v.y * w;
        acc.z += v.z * w; acc.w += v.w * w;
    }
    return acc;
}

// Layer 1: store aggregation to g_a (consumed by GEMM 2 with bias+relu)
__global__ void __launch_bounds__(128)
agg_csr_kernel() {
    int d = blockIdx.x;
    int t = threadIdx.x;
    ((float4*)g_a)[(size_t)d * 128 + t] = agg_row(d, t);
}

// Layer 2: aggregation fused with bias + relu + global max pool.
// 8 nodes per block, running column-max in registers, 1 atomicMax/col/block.
#define NPB 8
__global__ void __launch_bounds__(128)
agg_pool_kernel(const float* __restrict__ b2, float* __restrict__ out) {
    int t = threadIdx.x;
    int d0 = blockIdx.x * NPB;
    float4 bb = ((const float4*)b2)[t];
    float4 mx = make_float4(0.f, 0.f, 0.f, 0.f);
#pragma unroll
    for (int n = 0; n < NPB; n++) {
        float4 acc = agg_row(d0 + n, t);
        mx.x = fmaxf(mx.x, acc.x + bb.x);
        mx.y = fmaxf(mx.y, acc.y + bb.y);
        mx.z = fmaxf(mx.z, acc.z + bb.z);
        mx.w = fmaxf(mx.w, acc.w + bb.w);
    }
    // relu floor is the 0-init of out; values >= 0 -> int compare OK
    mx.x = fmaxf(mx.x, 0.f); mx.y = fmaxf(mx.y, 0.f);
    mx.z = fmaxf(mx.z, 0.f); mx.w = fmaxf(mx.w, 0.f);
    int* o = (int*)out;
    atomicMax(o + 4 * t + 0, __float_as_int(mx.x));
    atomicMax(o + 4 * t + 1, __float_as_int(mx.y));
    atomicMax(o + 4 * t + 2, __float_as_int(mx.z));
    atomicMax(o + 4 * t + 3, __float_as_int(mx.w));
}

__global__ void out_init_kernel(float* out) {
    int j = threadIdx.x;
    if (j < DIM) out[j] = 0.0f;
}

// ---------------------------------------------------------------------------
extern "C" void kernel_launch(void* const* d_in, const int* in_sizes, int n_in,
                              void* d_out, int out_size) {
    const float* X  = (const float*)d_in[0];
    const void*  ei = d_in[1];
    // d_in[2] = edge_attr (unused by GCNConv)
    const float* W1 = (const float*)d_in[3];
    const float* b1 = (const float*)d_in[4];
    const float* W2 = (const float*)d_in[5];
    const float* b2 = (const float*)d_in[6];
    float* out = (float*)d_out;

    // ---- edge index normalization (int32 vs int64 sniff + convert) ----
    flag_init_kernel<<<1, 1>>>();
    dtype_sniff_kernel<<<(NEDGES + 255) / 256, 256>>>((const int*)ei);
    edge_convert_kernel<<<(2 * NEDGES + 255) / 256, 256>>>(ei);

    // ---- normalization + CSR build ----
    deg_init_kernel<<<(NNODES + 255) / 256, 256>>>();
    deg_count_kernel<<<(NEDGES + 255) / 256, 256>>>();
    dinv_kernel<<<(NNODES + 255) / 256, 256>>>();
    scan_kernel<<<1, SCAN_T>>>();
    scatter_kernel<<<(NEDGES + 255) / 256, 256>>>();

    // ---- weight transposes (with tf32 pre-conversion) ----
    dim3 tgrid(16, 16), tblk(32, 32);
    transpose512_kernel<0><<<tgrid, tblk>>>(W1);
    transpose512_kernel<1><<<tgrid, tblk>>>(W2);
    out_init_kernel<<<1, DIM>>>(out);

    dim3 gemm_grid(DIM / 128, (NNODES + 127) / 128);  // (4, 157)

    // ---- layer 1: h = X @ W1 ; a = A_norm h ----
    mma_gemm_kernel<0><<<gemm_grid, 256>>>(X, nullptr);
    agg_csr_kernel<<<NNODES, 128>>>();

    // ---- layer 2: h = relu(a + b1) @ W2 ; fused agg + bias + relu + max pool ----
    mma_gemm_kernel<1><<<gemm_grid, 256>>>(nullptr, b1);
    agg_pool_kernel<<<NNODES / NPB, 128>>>(b2, out);
}

// round 11
// speedup vs baseline: 1.1432x; 1.1432x over previous
#include <cuda_runtime.h>
#include <cstdint>

#define NNODES 20000
#define NEDGES 320000
#define DIM    512

// Scratch (allocation-free rule: __device__ globals)
__device__ float g_h[(size_t)NNODES * DIM];   // GEMM output h = x @ W
__device__ float g_a[(size_t)NNODES * DIM];   // aggregation result
__device__ float g_dinv[NNODES];
__device__ int   g_deg[NNODES];
__device__ int   g_src[NEDGES];
__device__ int   g_dst[NEDGES];
__device__ int   g_is_i32;            // nonzero -> edge_index buffer is int32
__device__ int   g_rowptr[NNODES + 1];
__device__ int   g_cursor[NNODES];
__device__ int   g_csr_src[NEDGES];
__device__ float g_csr_w[NEDGES];
__device__ float g_w1t[DIM * DIM];    // W1^T (raw float; GEMM converts)
__device__ float g_w2t[DIM * DIM];    // W2^T (raw float; GEMM converts)

__device__ __forceinline__ uint32_t f2tf32(float f) {
    uint32_t r;
    asm("cvt.rna.tf32.f32 %0, %1;" : "=r"(r) : "f"(f));
    return r;
}

// ---------------------------------------------------------------------------
// Launch 1: flag + degree init
// ---------------------------------------------------------------------------
__global__ void init_kernel() {
    int i = blockIdx.x * blockDim.x + threadIdx.x;
    if (i == 0) g_is_i32 = 0;
    if (i < NNODES) g_deg[i] = 1;  // self-loop
}

// ---------------------------------------------------------------------------
// Launch 2: int32 vs int64 sniff (odd words all zero <=> int64)
// ---------------------------------------------------------------------------
__global__ void dtype_sniff_kernel(const int* __restrict__ ei32) {
    int i = blockIdx.x * blockDim.x + threadIdx.x;  // 0 .. E-1
    int acc = 0;
    if (i < NEDGES) acc = ei32[2 * i + 1];
#pragma unroll
    for (int o = 16; o > 0; o >>= 1) acc |= __shfl_xor_sync(0xffffffffu, acc, o);
    if ((threadIdx.x & 31) == 0 && acc != 0) atomicOr(&g_is_i32, 1);
}

// ---------------------------------------------------------------------------
// Launch 3: convert edge index to int32 + count in-degree
// ---------------------------------------------------------------------------
__global__ void convert_count_kernel(const void* __restrict__ ei) {
    int i = blockIdx.x * blockDim.x + threadIdx.x;  // 0 .. 2E-1
    if (i >= 2 * NEDGES) return;
    int v;
    if (g_is_i32) v = ((const int*)ei)[i];
    else          v = (int)((const long long*)ei)[i];
    if (i < NEDGES) {
        g_src[i] = v;
    } else {
        g_dst[i - NEDGES] = v;
        atomicAdd(&g_deg[v], 1);
    }
}

// ---------------------------------------------------------------------------
// Launch 4: dinv + exclusive prefix scan of (deg-1) -> rowptr, cursor. 1 block.
// ---------------------------------------------------------------------------
#define SCAN_T 1024
__global__ void scan_dinv_kernel() {
    __shared__ int sums[SCAN_T];
    const int CH = (NNODES + SCAN_T - 1) / SCAN_T;  // 20
    int t = threadIdx.x;
    int base = t * CH;
    int local = 0;
#pragma unroll
    for (int i = 0; i < CH; i++) {
        int idx = base + i;
        if (idx < NNODES) {
            int dg = g_deg[idx];
            g_dinv[idx] = rsqrtf((float)dg);
            local += dg - 1;
        }
    }
    sums[t] = local;
    __syncthreads();
    for (int o = 1; o < SCAN_T; o <<= 1) {
        int v = (t >= o) ? sums[t - o] : 0;
        __syncthreads();
        sums[t] += v;
        __syncthreads();
    }
    int run = (t > 0) ? sums[t - 1] : 0;
#pragma unroll
    for (int i = 0; i < CH; i++) {
        int idx = base + i;
        if (idx < NNODES) {
            g_rowptr[idx] = run;
            g_cursor[idx] = run;
            run += g_deg[idx] - 1;
        }
    }
    if (t == SCAN_T - 1) g_rowptr[NNODES] = sums[SCAN_T - 1];
}

// ---------------------------------------------------------------------------
// Launch 5 (fused): CSR scatter | W transposes | out init.  256 threads/block.
//   blocks [0, 1250)        : scatter edge e = b*256 + t
//   blocks [1250, 1250+512) : transpose one 32x32 tile (256 tiles per matrix)
//   block  1762             : zero out[0..511]
// ---------------------------------------------------------------------------
#define SCAT_BLKS (NEDGES / 256)              // 1250
#define TRAN_BLKS 512                          // 2 matrices x 256 tiles
__global__ void misc_kernel(const float* __restrict__ W1,
                            const float* __restrict__ W2,
                            float* __restrict__ out) {
    int b = blockIdx.x;
    int t = threadIdx.x;
    if (b < SCAT_BLKS) {
        int e = b * 256 + t;
        int s = g_src[e];
        int d = g_dst[e];
        int pos = atomicAdd(&g_cursor[d], 1);
        g_csr_src[pos] = s;
        g_csr_w[pos] = g_dinv[s] * g_dinv[d];
        return;
    }
    if (b < SCAT_BLKS + TRAN_BLKS) {
        __shared__ float ts[32][33];
        int tile = b - SCAT_BLKS;
        const float* W = (tile >= 256) ? W2 : W1;
        float* o = (tile >= 256) ? g_w2t : g_w1t;
        int tl = tile & 255;
        int bx = (tl & 15) * 32, by = (tl >> 4) * 32;
        int r = t >> 3, c = (t & 7) * 4;
        float4 v = *(const float4*)&W[(size_t)(by + r) * DIM + bx + c];
        ts[r][c] = v.x; ts[r][c + 1] = v.y; ts[r][c + 2] = v.z; ts[r][c + 3] = v.w;
        __syncthreads();
        float4 ov = make_float4(ts[c][r], ts[c + 1][r], ts[c + 2][r], ts[c + 3][r]);
        *(float4*)&o[(size_t)(bx + r) * DIM + by + c] = ov;
        return;
    }
    // out init
    out[t] = 0.0f;
    out[t + 256] = 0.0f;
}

// ---------------------------------------------------------------------------
// Launch 6 (ncu capture slot): tensor-core GEMM via mma.sync tf32 (R6-exact):
//   g_h[M,512] = op(A)[M,512] @ W[512,512]
//   MODE 0: A = Aparam (raw),     B = g_w1t
//   MODE 1: A = relu(g_a + bias), B = g_w2t
// CTA 128x128, BK=32, 256 threads = 8 warps (4 M x 2 N), warp tile 32x64.
// ---------------------------------------------------------------------------
#define SMS 36  // smem row stride (32 + 4 pad)

template <int MODE>
__global__ void __launch_bounds__(256)
mma_gemm_kernel(const float* __restrict__ Aparam, const float* __restrict__ bias) {
    __shared__ uint32_t As[128 * SMS];
    __shared__ uint32_t Bs[128 * SMS];

    const float* A  = (MODE == 0) ? Aparam : g_a;
    const float* Bt = (MODE == 0) ? g_w1t : g_w2t;

    int tid = threadIdx.x, wid = tid >> 5, lane = tid & 31;
    int row0 = blockIdx.y * 128;
    int col0 = blockIdx.x * 128;
    int wm = (wid & 3) * 32;   // warp M offset in tile
    int wn = (wid >> 2) * 64;  // warp N offset in tile
    int gq = lane >> 2;        // group id (0..7)
    int tq = lane & 3;         // thread-in-group (0..3)

    float acc[2][8][4];
#pragma unroll
    for (int mt = 0; mt < 2; mt++)
#pragma unroll
        for (int nt = 0; nt < 8; nt++)
#pragma unroll
            for (int j = 0; j < 4; j++) acc[mt][nt][j] = 0.f;

    for (int kc = 0; kc < DIM; kc += 32) {
        // ---- load A tile: 128 rows x 32 cols, 4 float4 per thread ----
#pragma unroll
        for (int i = 0; i < 4; i++) {
            int idx = tid + 256 * i;
            int r = idx >> 3, c4 = idx & 7;
            int grow = row0 + r;
            float4 v = make_float4(0.f, 0.f, 0.f, 0.f);
            if (grow < NNODES)
                v = *(const float4*)&A[(size_t)grow * DIM + kc + c4 * 4];
            if (MODE == 1) {
                float4 bb = *(const float4*)&bias[kc + c4 * 4];
                v.x = fmaxf(v.x + bb.x, 0.f);
                v.y = fmaxf(v.y + bb.y, 0.f);
                v.z = fmaxf(v.z + bb.z, 0.f);
                v.w = fmaxf(v.w + bb.w, 0.f);
            }
            uint4 tv = make_uint4(f2tf32(v.x), f2tf32(v.y), f2tf32(v.z), f2tf32(v.w));
            *(uint4*)&As[r * SMS + c4 * 4] = tv;
        }
        // ---- load B tile: rows n = col0..+127 of Wt[N][K] ----
#pragma unroll
        for (int i = 0; i < 4; i++) {
            int idx = tid + 256 * i;
            int r = idx >> 3, c4 = idx & 7;
            float4 v = *(const float4*)&Bt[(size_t)(col0 + r) * DIM + kc + c4 * 4];
            uint4 tv = make_uint4(f2tf32(v.x), f2tf32(v.y), f2tf32(v.z), f2tf32(v.w));
            *(uint4*)&Bs[r * SMS + c4 * 4] = tv;
        }
        __syncthreads();

#pragma unroll
        for (int ks = 0; ks < 4; ks++) {
            int k0 = ks * 8;
            uint32_t af[2][4], bf[8][2];
#pragma unroll
            for (int mt = 0; mt < 2; mt++) {
                int r = wm + mt * 16 + gq;
                af[mt][0] = As[r * SMS + k0 + tq];
                af[mt][1] = As[(r + 8) * SMS + k0 + tq];
                af[mt][2] = As[r * SMS + k0 + tq + 4];
                af[mt][3] = As[(r + 8) * SMS + k0 + tq + 4];
            }
#pragma unroll
            for (int nt = 0; nt < 8; nt++) {
                int n = wn + nt * 8 + gq;
                bf[nt][0] = Bs[n * SMS + k0 + tq];
                bf[nt][1] = Bs[n * SMS + k0 + tq + 4];
            }
#pragma unroll
            for (int mt = 0; mt < 2; mt++)
#pragma unroll
                for (int nt = 0; nt < 8; nt++) {
                    asm volatile(
                        "mma.sync.aligned.m16n8k8.row.col.f32.tf32.tf32.f32 "
                        "{%0,%1,%2,%3}, {%4,%5,%6,%7}, {%8,%9}, {%0,%1,%2,%3};"
                        : "+f"(acc[mt][nt][0]), "+f"(acc[mt][nt][1]),
                          "+f"(acc[mt][nt][2]), "+f"(acc[mt][nt][3])
                        : "r"(af[mt][0]), "r"(af[mt][1]),
                          "r"(af[mt][2]), "r"(af[mt][3]),
                          "r"(bf[nt][0]), "r"(bf[nt][1]));
                }
        }
        __syncthreads();
    }

    // ---- epilogue: fragments -> g_h ----
#pragma unroll
    for (int mt = 0; mt < 2; mt++) {
        int r0 = row0 + wm + mt * 16 + gq;
#pragma unroll
        for (int nt = 0; nt < 8; nt++) {
            int c = col0 + wn + nt * 8 + tq * 2;
            if (r0 < NNODES)
                *(float2*)&g_h[(size_t)r0 * DIM + c] =
                    make_float2(acc[mt][nt][0], acc[mt][nt][1]);
            if (r0 + 8 < NNODES)
                *(float2*)&g_h[(size_t)(r0 + 8) * DIM + c] =
                    make_float2(acc[mt][nt][2], acc[mt][nt][3]);
        }
    }
}

// ---------------------------------------------------------------------------
// CSR aggregation (atomic-free, self-loop fused):
//   a[d,:] = dinv[d]^2 * h[d,:] + sum_{e: dst=d} w_e * h[src_e,:]
// one 128-thread block per node; each thread owns one float4 of the row.
// ---------------------------------------------------------------------------
__global__ void __launch_bounds__(128)
agg_csr_kernel() {
    int d = blockIdx.x;
    int t = threadIdx.x;  // 0..127 -> float4 column
    const float4* __restrict__ h4 = (const float4*)g_h;

    float dv = g_dinv[d];
    float4 acc = h4[(size_t)d * 128 + t];
    float ws = dv * dv;
    acc.x *= ws; acc.y *= ws; acc.z *= ws; acc.w *= ws;

    int j   = g_rowptr[d];
    int end = g_rowptr[d + 1];

    for (; j + 4 <= end; j += 4) {
        int   s0 = g_csr_src[j],     s1 = g_csr_src[j + 1];
        int   s2 = g_csr_src[j + 2], s3 = g_csr_src[j + 3];
        float w0 = g_csr_w[j],       w1 = g_csr_w[j + 1];
        float w2 = g_csr_w[j + 2],   w3 = g_csr_w[j + 3];
        float4 v0 = h4[(size_t)s0 * 128 + t];
        float4 v1 = h4[(size_t)s1 * 128 + t];
        float4 v2 = h4[(size_t)s2 * 128 + t];
        float4 v3 = h4[(size_t)s3 * 128 + t];
        acc.x += v0.x * w0 + v1.x * w1 + v2.x * w2 + v3.x * w3;
        acc.y += v0.y * w0 + v1.y * w1 + v2.y * w2 + v3.y * w3;
        acc.z += v0.z * w0 + v1.z * w1 + v2.z * w2 + v3.z * w3;
        acc.w += v0.w * w0 + v1.w * w1 + v2.w * w2 + v3.w * w3;
    }
    for (; j < end; j++) {
        int   s = g_csr_src[j];
        float w = g_csr_w[j];
        float4 v = h4[(size_t)s * 128 + t];
        acc.x += v.x * w; acc.y += v.y * w;
        acc.z += v.z * w; acc.w += v.w * w;
    }

    ((float4*)g_a)[(size_t)d * 128 + t] = acc;
}

// ---------------------------------------------------------------------------
// Max pool: out[j] = max_i relu(a[i,j] + b2[j])   (out pre-zeroed in misc)
// ---------------------------------------------------------------------------
#define POOL_ROWS 100
__global__ void maxpool_kernel(const float* __restrict__ b2, float* __restrict__ out) {
    int col  = threadIdx.x;   // 512 threads
    int row0 = blockIdx.x * POOL_ROWS;
    float bb = b2[col];
    float m = 0.f;
#pragma unroll 4
    for (int r = 0; r < POOL_ROWS; r++) {
        int row = row0 + r;
        if (row >= NNODES) break;
        float v = g_a[(size_t)row * DIM + col] + bb;
        m = fmaxf(m, fmaxf(v, 0.f));
    }
    // all values >= 0 -> int-reinterpreted compare is order-preserving
    atomicMax((int*)out + col, __float_as_int(m));
}

// ---------------------------------------------------------------------------
extern "C" void kernel_launch(void* const* d_in, const int* in_sizes, int n_in,
                              void* d_out, int out_size) {
    const float* X  = (const float*)d_in[0];
    const void*  ei = d_in[1];
    // d_in[2] = edge_attr (unused by GCNConv)
    const float* W1 = (const float*)d_in[3];
    const float* b1 = (const float*)d_in[4];
    const float* W2 = (const float*)d_in[5];
    const float* b2 = (const float*)d_in[6];
    float* out = (float*)d_out;

    // ---- prep: exactly 5 launches so launch #6 = GEMM0 (ncu -s 5 -c 1) ----
    init_kernel<<<(NNODES + 255) / 256, 256>>>();                       // 1
    dtype_sniff_kernel<<<(NEDGES + 255) / 256, 256>>>((const int*)ei);  // 2
    convert_count_kernel<<<(2 * NEDGES + 255) / 256, 256>>>(ei);        // 3
    scan_dinv_kernel<<<1, SCAN_T>>>();                                  // 4
    misc_kernel<<<SCAT_BLKS + TRAN_BLKS + 1, 256>>>(W1, W2, out);       // 5

    dim3 gemm_grid(DIM / 128, (NNODES + 127) / 128);  // (4, 157)

    // ---- layer 1: h = X @ W1 ; a = A_norm h ----
    mma_gemm_kernel<0><<<gemm_grid, 256>>>(X, nullptr);                 // 6 <- profiled
    agg_csr_kernel<<<NNODES, 128>>>();

    // ---- layer 2: h = relu(a + b1) @ W2 ; a = A_norm h ----
    mma_gemm_kernel<1><<<gemm_grid, 256>>>(nullptr, b1);
    agg_csr_kernel<<<NNODES, 128>>>();

    // ---- global max pool over relu(a + b2) ----
    maxpool_kernel<<<(NNODES + POOL_ROWS - 1) / POOL_ROWS, DIM>>>(b2, out);
}

// round 12
// speedup vs baseline: 1.1825x; 1.0344x over previous
#include <cuda_runtime.h>
#include <cstdint>

#define NNODES 20000
#define NEDGES 320000
#define DIM    512

// Scratch (allocation-free rule: __device__ globals)
__device__ float g_h[(size_t)NNODES * DIM];   // GEMM output h = x @ W
__device__ float g_a[(size_t)NNODES * DIM];   // aggregation result
__device__ float g_dinv[NNODES];
__device__ int   g_deg[NNODES];
__device__ int   g_src[NEDGES];
__device__ int   g_dst[NEDGES];
__device__ int   g_is_i32;            // nonzero -> edge_index buffer is int32
__device__ int   g_rowptr[NNODES + 1];
__device__ int   g_cursor[NNODES];
__device__ int   g_csr_src[NEDGES];
__device__ float g_csr_w[NEDGES];
__device__ float g_w1t[DIM * DIM];    // W1^T (raw float; GEMM converts)
__device__ float g_w2t[DIM * DIM];    // W2^T (raw float; GEMM converts)

__device__ __forceinline__ uint32_t f2tf32(float f) {
    uint32_t r;
    asm("cvt.rna.tf32.f32 %0, %1;" : "=r"(r) : "f"(f));
    return r;
}

// ---------------------------------------------------------------------------
// Launch 1 (fused): deg init | W transposes | out init + flag init
//   blocks [0, 79)    : deg init
//   blocks [79, 591)  : transpose one 32x32 tile (256 tiles per matrix)
//   block  591        : zero out[0..511], reset dtype flag
// ---------------------------------------------------------------------------
#define DEGI_BLKS 79
#define TRAN_BLKS 512
__global__ void init_misc_kernel(const float* __restrict__ W1,
                                 const float* __restrict__ W2,
                                 float* __restrict__ out) {
    int b = blockIdx.x;
    int t = threadIdx.x;
    if (b < DEGI_BLKS) {
        int i = b * 256 + t;
        if (i < NNODES) g_deg[i] = 1;  // self-loop
        return;
    }
    if (b < DEGI_BLKS + TRAN_BLKS) {
        __shared__ float ts[32][33];
        int tile = b - DEGI_BLKS;
        const float* W = (tile >= 256) ? W2 : W1;
        float* o = (tile >= 256) ? g_w2t : g_w1t;
        int tl = tile & 255;
        int bx = (tl & 15) * 32, by = (tl >> 4) * 32;
        int r = t >> 3, c = (t & 7) * 4;
        float4 v = *(const float4*)&W[(size_t)(by + r) * DIM + bx + c];
        ts[r][c] = v.x; ts[r][c + 1] = v.y; ts[r][c + 2] = v.z; ts[r][c + 3] = v.w;
        __syncthreads();
        float4 ov = make_float4(ts[c][r], ts[c + 1][r], ts[c + 2][r], ts[c + 3][r]);
        *(float4*)&o[(size_t)(bx + r) * DIM + by + c] = ov;
        return;
    }
    // out init + flag reset
    out[t] = 0.0f;
    out[t + 256] = 0.0f;
    if (t == 0) g_is_i32 = 0;
}

// ---------------------------------------------------------------------------
// Launch 2: int32 vs int64 sniff (odd words all zero <=> int64)
// ---------------------------------------------------------------------------
__global__ void dtype_sniff_kernel(const int* __restrict__ ei32) {
    int i = blockIdx.x * blockDim.x + threadIdx.x;  // 0 .. E-1
    int acc = 0;
    if (i < NEDGES) acc = ei32[2 * i + 1];
#pragma unroll
    for (int o = 16; o > 0; o >>= 1) acc |= __shfl_xor_sync(0xffffffffu, acc, o);
    if ((threadIdx.x & 31) == 0 && acc != 0) atomicOr(&g_is_i32, 1);
}

// ---------------------------------------------------------------------------
// Launch 3: convert edge index to int32 + count in-degree
// ---------------------------------------------------------------------------
__global__ void convert_count_kernel(const void* __restrict__ ei) {
    int i = blockIdx.x * blockDim.x + threadIdx.x;  // 0 .. 2E-1
    if (i >= 2 * NEDGES) return;
    int v;
    if (g_is_i32) v = ((const int*)ei)[i];
    else          v = (int)((const long long*)ei)[i];
    if (i < NEDGES) {
        g_src[i] = v;
    } else {
        g_dst[i - NEDGES] = v;
        atomicAdd(&g_deg[v], 1);
    }
}

// ---------------------------------------------------------------------------
// Launch 4 (profiled slot): tensor-core GEMM via mma.sync tf32:
//   g_h[M,512] = op(A)[M,512] @ W[512,512]
//   MODE 0: A = Aparam (raw),     B = g_w1t
//   MODE 1: A = relu(g_a + bias), B = g_w2t
// CTA 128x128, BK=32, 256 threads = 8 warps (4 M x 2 N), warp tile 32x64.
// ---------------------------------------------------------------------------
#define SMS 36  // smem row stride (32 + 4 pad)

template <int MODE>
__global__ void __launch_bounds__(256)
mma_gemm_kernel(const float* __restrict__ Aparam, const float* __restrict__ bias) {
    __shared__ uint32_t As[128 * SMS];
    __shared__ uint32_t Bs[128 * SMS];

    const float* A  = (MODE == 0) ? Aparam : g_a;
    const float* Bt = (MODE == 0) ? g_w1t : g_w2t;

    int tid = threadIdx.x, wid = tid >> 5, lane = tid & 31;
    int row0 = blockIdx.y * 128;
    int col0 = blockIdx.x * 128;
    int wm = (wid & 3) * 32;   // warp M offset in tile
    int wn = (wid >> 2) * 64;  // warp N offset in tile
    int gq = lane >> 2;        // group id (0..7)
    int tq = lane & 3;         // thread-in-group (0..3)

    float acc[2][8][4];
#pragma unroll
    for (int mt = 0; mt < 2; mt++)
#pragma unroll
        for (int nt = 0; nt < 8; nt++)
#pragma unroll
            for (int j = 0; j < 4; j++) acc[mt][nt][j] = 0.f;

    for (int kc = 0; kc < DIM; kc += 32) {
        // ---- load A tile: 128 rows x 32 cols, 4 float4 per thread ----
#pragma unroll
        for (int i = 0; i < 4; i++) {
            int idx = tid + 256 * i;
            int r = idx >> 3, c4 = idx & 7;
            int grow = row0 + r;
            float4 v = make_float4(0.f, 0.f, 0.f, 0.f);
            if (grow < NNODES)
                v = *(const float4*)&A[(size_t)grow * DIM + kc + c4 * 4];
            if (MODE == 1) {
                float4 bb = *(const float4*)&bias[kc + c4 * 4];
                v.x = fmaxf(v.x + bb.x, 0.f);
                v.y = fmaxf(v.y + bb.y, 0.f);
                v.z = fmaxf(v.z + bb.z, 0.f);
                v.w = fmaxf(v.w + bb.w, 0.f);
            }
            uint4 tv = make_uint4(f2tf32(v.x), f2tf32(v.y), f2tf32(v.z), f2tf32(v.w));
            *(uint4*)&As[r * SMS + c4 * 4] = tv;
        }
        // ---- load B tile: rows n = col0..+127 of Wt[N][K] ----
#pragma unroll
        for (int i = 0; i < 4; i++) {
            int idx = tid + 256 * i;
            int r = idx >> 3, c4 = idx & 7;
            float4 v = *(const float4*)&Bt[(size_t)(col0 + r) * DIM + kc + c4 * 4];
            uint4 tv = make_uint4(f2tf32(v.x), f2tf32(v.y), f2tf32(v.z), f2tf32(v.w));
            *(uint4*)&Bs[r * SMS + c4 * 4] = tv;
        }
        __syncthreads();

#pragma unroll
        for (int ks = 0; ks < 4; ks++) {
            int k0 = ks * 8;
            uint32_t af[2][4], bf[8][2];
#pragma unroll
            for (int mt = 0; mt < 2; mt++) {
                int r = wm + mt * 16 + gq;
                af[mt][0] = As[r * SMS + k0 + tq];
                af[mt][1] = As[(r + 8) * SMS + k0 + tq];
                af[mt][2] = As[r * SMS + k0 + tq + 4];
                af[mt][3] = As[(r + 8) * SMS + k0 + tq + 4];
            }
#pragma unroll
            for (int nt = 0; nt < 8; nt++) {
                int n = wn + nt * 8 + gq;
                bf[nt][0] = Bs[n * SMS + k0 + tq];
                bf[nt][1] = Bs[n * SMS + k0 + tq + 4];
            }
#pragma unroll
            for (int mt = 0; mt < 2; mt++)
#pragma unroll
                for (int nt = 0; nt < 8; nt++) {
                    asm volatile(
                        "mma.sync.aligned.m16n8k8.row.col.f32.tf32.tf32.f32 "
                        "{%0,%1,%2,%3}, {%4,%5,%6,%7}, {%8,%9}, {%0,%1,%2,%3};"
                        : "+f"(acc[mt][nt][0]), "+f"(acc[mt][nt][1]),
                          "+f"(acc[mt][nt][2]), "+f"(acc[mt][nt][3])
                        : "r"(af[mt][0]), "r"(af[mt][1]),
                          "r"(af[mt][2]), "r"(af[mt][3]),
                          "r"(bf[nt][0]), "r"(bf[nt][1]));
                }
        }
        __syncthreads();
    }

    // ---- epilogue: fragments -> g_h ----
#pragma unroll
    for (int mt = 0; mt < 2; mt++) {
        int r0 = row0 + wm + mt * 16 + gq;
#pragma unroll
        for (int nt = 0; nt < 8; nt++) {
            int c = col0 + wn + nt * 8 + tq * 2;
            if (r0 < NNODES)
                *(float2*)&g_h[(size_t)r0 * DIM + c] =
                    make_float2(acc[mt][nt][0], acc[mt][nt][1]);
            if (r0 + 8 < NNODES)
                *(float2*)&g_h[(size_t)(r0 + 8) * DIM + c] =
                    make_float2(acc[mt][nt][2], acc[mt][nt][3]);
        }
    }
}

// ---------------------------------------------------------------------------
// Launch 5: dinv + coalesced smem prefix scan of (deg-1) -> rowptr, cursor.
// 1 block, 1024 threads, 84KB dynamic smem.
// ---------------------------------------------------------------------------
#define SCAN_T 1024
#define SCAN_CH ((NNODES + SCAN_T - 1) / SCAN_T)   // 20
#define SCAN_SMEM ((NNODES + SCAN_T) * 4)          // deg-vals + partials
__global__ void scan_dinv_kernel() {
    extern __shared__ int sm[];     // [0,NNODES): deg-1 / run values; [NNODES,+1024): partials
    int* sums = sm + NNODES;
    int t = threadIdx.x;

    // coalesced load + dinv
    for (int i = t; i < NNODES; i += SCAN_T) {
        int dg = g_deg[i];
        g_dinv[i] = rsqrtf((float)dg);
        sm[i] = dg - 1;
    }
    __syncthreads();

    // per-thread serial chunk sum (smem)
    int base = t * SCAN_CH;
    int local = 0;
#pragma unroll
    for (int i = 0; i < SCAN_CH; i++) {
        int idx = base + i;
        if (idx < NNODES) local += sm[idx];
    }
    sums[t] = local;
    __syncthreads();
    for (int o = 1; o < SCAN_T; o <<= 1) {
        int v = (t >= o) ? sums[t - o] : 0;
        __syncthreads();
        sums[t] += v;
        __syncthreads();
    }
    int run = (t > 0) ? sums[t - 1] : 0;
    // in-place: replace counts with exclusive prefix
#pragma unroll
    for (int i = 0; i < SCAN_CH; i++) {
        int idx = base + i;
        if (idx < NNODES) {
            int v = sm[idx];
            sm[idx] = run;
            run += v;
        }
    }
    __syncthreads();
    // coalesced store
    for (int i = t; i < NNODES; i += SCAN_T) {
        int r = sm[i];
        g_rowptr[i] = r;
        g_cursor[i] = r;
    }
    if (t == SCAN_T - 1) g_rowptr[NNODES] = sums[SCAN_T - 1];
}

// ---------------------------------------------------------------------------
// Launch 6: scatter edges into CSR (by dst), precomputing edge weight
// ---------------------------------------------------------------------------
__global__ void scatter_kernel() {
    int e = blockIdx.x * blockDim.x + threadIdx.x;
    if (e >= NEDGES) return;
    int s = g_src[e];
    int d = g_dst[e];
    int pos = atomicAdd(&g_cursor[d], 1);
    g_csr_src[pos] = s;
    g_csr_w[pos] = g_dinv[s] * g_dinv[d];
}

// ---------------------------------------------------------------------------
// CSR aggregation (atomic-free, self-loop fused):
//   a[d,:] = dinv[d]^2 * h[d,:] + sum_{e: dst=d} w_e * h[src_e,:]
// ---------------------------------------------------------------------------
__global__ void __launch_bounds__(128)
agg_csr_kernel() {
    int d = blockIdx.x;
    int t = threadIdx.x;  // 0..127 -> float4 column
    const float4* __restrict__ h4 = (const float4*)g_h;

    float dv = g_dinv[d];
    float4 acc = h4[(size_t)d * 128 + t];
    float ws = dv * dv;
    acc.x *= ws; acc.y *= ws; acc.z *= ws; acc.w *= ws;

    int j   = g_rowptr[d];
    int end = g_rowptr[d + 1];

    for (; j + 4 <= end; j += 4) {
        int   s0 = g_csr_src[j],     s1 = g_csr_src[j + 1];
        int   s2 = g_csr_src[j + 2], s3 = g_csr_src[j + 3];
        float w0 = g_csr_w[j],       w1 = g_csr_w[j + 1];
        float w2 = g_csr_w[j + 2],   w3 = g_csr_w[j + 3];
        float4 v0 = h4[(size_t)s0 * 128 + t];
        float4 v1 = h4[(size_t)s1 * 128 + t];
        float4 v2 = h4[(size_t)s2 * 128 + t];
        float4 v3 = h4[(size_t)s3 * 128 + t];
        acc.x += v0.x * w0 + v1.x * w1 + v2.x * w2 + v3.x * w3;
        acc.y += v0.y * w0 + v1.y * w1 + v2.y * w2 + v3.y * w3;
        acc.z += v0.z * w0 + v1.z * w1 + v2.z * w2 + v3.z * w3;
        acc.w += v0.w * w0 + v1.w * w1 + v2.w * w2 + v3.w * w3;
    }
    for (; j < end; j++) {
        int   s = g_csr_src[j];
        float w = g_csr_w[j];
        float4 v = h4[(size_t)s * 128 + t];
        acc.x += v.x * w; acc.y += v.y * w;
        acc.z += v.z * w; acc.w += v.w * w;
    }

    ((float4*)g_a)[(size_t)d * 128 + t] = acc;
}

// ---------------------------------------------------------------------------
// Max pool: out[j] = max_i relu(a[i,j] + b2[j])   (out pre-zeroed in launch 1)
// ---------------------------------------------------------------------------
#define POOL_ROWS 100
__global__ void maxpool_kernel(const float* __restrict__ b2, float* __restrict__ out) {
    int col  = threadIdx.x;   // 512 threads
    int row0 = blockIdx.x * POOL_ROWS;
    float bb = b2[col];
    float m = 0.f;
#pragma unroll 4
    for (int r = 0; r < POOL_ROWS; r++) {
        int row = row0 + r;
        if (row >= NNODES) break;
        float v = g_a[(size_t)row * DIM + col] + bb;
        m = fmaxf(m, fmaxf(v, 0.f));
    }
    // all values >= 0 -> int-reinterpreted compare is order-preserving
    atomicMax((int*)out + col, __float_as_int(m));
}

// ---------------------------------------------------------------------------
extern "C" void kernel_launch(void* const* d_in, const int* in_sizes, int n_in,
                              void* d_out, int out_size) {
    const float* X  = (const float*)d_in[0];
    const void*  ei = d_in[1];
    // d_in[2] = edge_attr (unused by GCNConv)
    const float* W1 = (const float*)d_in[3];
    const float* b1 = (const float*)d_in[4];
    const float* W2 = (const float*)d_in[5];
    const float* b2 = (const float*)d_in[6];
    float* out = (float*)d_out;

    cudaFuncSetAttribute(scan_dinv_kernel,
                         cudaFuncAttributeMaxDynamicSharedMemorySize, SCAN_SMEM);

    dim3 gemm_grid(DIM / 128, (NNODES + 127) / 128);  // (4, 157)

    // 1: deg init | W transposes | out init | flag reset
    init_misc_kernel<<<DEGI_BLKS + TRAN_BLKS + 1, 256>>>(W1, W2, out);
    // 2: dtype sniff
    dtype_sniff_kernel<<<(NEDGES + 255) / 256, 256>>>((const int*)ei);
    // 3: edge convert + degree count
    convert_count_kernel<<<(2 * NEDGES + 255) / 256, 256>>>(ei);
    // 4: layer-1 GEMM (profiled slot)  h = X @ W1
    mma_gemm_kernel<0><<<gemm_grid, 256>>>(X, nullptr);
    // 5: dinv + rowptr scan
    scan_dinv_kernel<<<1, SCAN_T, SCAN_SMEM>>>();
    // 6: CSR scatter
    scatter_kernel<<<(NEDGES + 255) / 256, 256>>>();
    // 7: layer-1 aggregation  a = A_norm h
    agg_csr_kernel<<<NNODES, 128>>>();
    // 8: layer-2 GEMM  h = relu(a + b1) @ W2
    mma_gemm_kernel<1><<<gemm_grid, 256>>>(nullptr, b1);
    // 9: layer-2 aggregation
    agg_csr_kernel<<<NNODES, 128>>>();
    // 10: global max pool over relu(a + b2)
    maxpool_kernel<<<(NNODES + POOL_ROWS - 1) / POOL_ROWS, DIM>>>(b2, out);
}

// round 13
// speedup vs baseline: 1.2959x; 1.0959x over previous
#include <cuda_runtime.h>
#include <cstdint>

#define NNODES 20000
#define NEDGES 320000
#define DIM    512

// Scratch (allocation-free rule: __device__ globals)
__device__ float g_h[(size_t)NNODES * DIM];   // GEMM output h = x @ W
__device__ float g_a[(size_t)NNODES * DIM];   // GEMM A operand (tf32 bits)
__device__ float g_dinv[NNODES];
__device__ int   g_deg[NNODES];
__device__ int   g_src[NEDGES];
__device__ int   g_dst[NEDGES];
__device__ int   g_is_i32;            // nonzero -> edge_index buffer is int32
__device__ int   g_rowptr[NNODES + 1];
__device__ int   g_cursor[NNODES];
__device__ int   g_csr_src[NEDGES];
__device__ float g_csr_w[NEDGES];
__device__ float g_w1t[DIM * DIM];    // W1^T, tf32 bits
__device__ float g_w2t[DIM * DIM];    // W2^T, tf32 bits

__device__ __forceinline__ uint32_t f2tf32(float f) {
    uint32_t r;
    asm("cvt.rna.tf32.f32 %0, %1;" : "=r"(r) : "f"(f));
    return r;
}

// ---------------------------------------------------------------------------
// Launch 1 (fused): deg init | W transpose+tf32 | X->tf32 | out init + flag
//   blocks [0, 79)          : deg init
//   blocks [79, 591)        : transpose one 32x32 tile (256 tiles per matrix)
//   blocks [591, 10591)     : X -> tf32 bits into g_a (256 float4 per block)
//   block  10591            : zero out[0..511], reset dtype flag
// ---------------------------------------------------------------------------
#define DEGI_BLKS 79
#define TRAN_BLKS 512
#define XCNV_BLKS (NNODES * (DIM / 4) / 256)   // 10000
__global__ void init_misc_kernel(const float* __restrict__ X,
                                 const float* __restrict__ W1,
                                 const float* __restrict__ W2,
                                 float* __restrict__ out) {
    int b = blockIdx.x;
    int t = threadIdx.x;
    if (b < DEGI_BLKS) {
        int i = b * 256 + t;
        if (i < NNODES) g_deg[i] = 1;  // self-loop
        return;
    }
    if (b < DEGI_BLKS + TRAN_BLKS) {
        __shared__ float ts[32][33];
        int tile = b - DEGI_BLKS;
        const float* W = (tile >= 256) ? W2 : W1;
        float* o = (tile >= 256) ? g_w2t : g_w1t;
        int tl = tile & 255;
        int bx = (tl & 15) * 32, by = (tl >> 4) * 32;
        int r = t >> 3, c = (t & 7) * 4;
        float4 v = *(const float4*)&W[(size_t)(by + r) * DIM + bx + c];
        ts[r][c] = v.x; ts[r][c + 1] = v.y; ts[r][c + 2] = v.z; ts[r][c + 3] = v.w;
        __syncthreads();
        // transpose + tf32 pre-conversion
        uint4 ov = make_uint4(f2tf32(ts[c][r]),     f2tf32(ts[c + 1][r]),
                              f2tf32(ts[c + 2][r]), f2tf32(ts[c + 3][r]));
        *(uint4*)&o[(size_t)(bx + r) * DIM + by + c] = ov;
        return;
    }
    if (b < DEGI_BLKS + TRAN_BLKS + XCNV_BLKS) {
        int idx = (b - DEGI_BLKS - TRAN_BLKS) * 256 + t;
        float4 v = ((const float4*)X)[idx];
        ((uint4*)g_a)[idx] =
            make_uint4(f2tf32(v.x), f2tf32(v.y), f2tf32(v.z), f2tf32(v.w));
        return;
    }
    // out init + flag reset
    out[t] = 0.0f;
    out[t + 256] = 0.0f;
    if (t == 0) g_is_i32 = 0;
}

// ---------------------------------------------------------------------------
// Launch 2: int32 vs int64 sniff (odd words all zero <=> int64)
// ---------------------------------------------------------------------------
__global__ void dtype_sniff_kernel(const int* __restrict__ ei32) {
    int i = blockIdx.x * blockDim.x + threadIdx.x;  // 0 .. E-1
    int acc = 0;
    if (i < NEDGES) acc = ei32[2 * i + 1];
#pragma unroll
    for (int o = 16; o > 0; o >>= 1) acc |= __shfl_xor_sync(0xffffffffu, acc, o);
    if ((threadIdx.x & 31) == 0 && acc != 0) atomicOr(&g_is_i32, 1);
}

// ---------------------------------------------------------------------------
// Launch 3: convert edge index to int32 + count in-degree
// ---------------------------------------------------------------------------
__global__ void convert_count_kernel(const void* __restrict__ ei) {
    int i = blockIdx.x * blockDim.x + threadIdx.x;  // 0 .. 2E-1
    if (i >= 2 * NEDGES) return;
    int v;
    if (g_is_i32) v = ((const int*)ei)[i];
    else          v = (int)((const long long*)ei)[i];
    if (i < NEDGES) {
        g_src[i] = v;
    } else {
        g_dst[i - NEDGES] = v;
        atomicAdd(&g_deg[v], 1);
    }
}

// ---------------------------------------------------------------------------
// Launch 4 (profiled slot): cp.async double-buffered tensor-core GEMM (tf32):
//   g_h[M,512] = g_a[M,512] @ Wt^T   (Wt = g_w1t MODE 0, g_w2t MODE 1)
// CTA 128x128, BK=32, 256 threads = 8 warps (4 M x 2 N), warp tile 32x64.
// Operands pre-converted to tf32 -> pure copy on the load path.
// ---------------------------------------------------------------------------
#define SMS 36                            // smem row stride (32 + 4 pad)
#define SM_BUF (128 * SMS)                // words per tile buffer
#define GEMM_SMEM_BYTES (4 * SM_BUF * 4)  // [A0 B0 A1 B1]

__device__ __forceinline__ void cp16(uint32_t dst, const void* src) {
    asm volatile("cp.async.cg.shared.global [%0], [%1], 16;"
                 :: "r"(dst), "l"(src));
}

__device__ __forceinline__ void mma_ks(const uint32_t* __restrict__ As_,
                                       const uint32_t* __restrict__ Bs_,
                                       float (&acc)[2][8][4],
                                       int k0, int wm, int wn, int gq, int tq) {
    uint32_t af[2][4], bf[8][2];
#pragma unroll
    for (int mt = 0; mt < 2; mt++) {
        int r = wm + mt * 16 + gq;
        af[mt][0] = As_[r * SMS + k0 + tq];
        af[mt][1] = As_[(r + 8) * SMS + k0 + tq];
        af[mt][2] = As_[r * SMS + k0 + tq + 4];
        af[mt][3] = As_[(r + 8) * SMS + k0 + tq + 4];
    }
#pragma unroll
    for (int nt = 0; nt < 8; nt++) {
        int n = wn + nt * 8 + gq;
        bf[nt][0] = Bs_[n * SMS + k0 + tq];
        bf[nt][1] = Bs_[n * SMS + k0 + tq + 4];
    }
#pragma unroll
    for (int mt = 0; mt < 2; mt++)
#pragma unroll
        for (int nt = 0; nt < 8; nt++) {
            asm volatile(
                "mma.sync.aligned.m16n8k8.row.col.f32.tf32.tf32.f32 "
                "{%0,%1,%2,%3}, {%4,%5,%6,%7}, {%8,%9}, {%0,%1,%2,%3};"
                : "+f"(acc[mt][nt][0]), "+f"(acc[mt][nt][1]),
                  "+f"(acc[mt][nt][2]), "+f"(acc[mt][nt][3])
                : "r"(af[mt][0]), "r"(af[mt][1]),
                  "r"(af[mt][2]), "r"(af[mt][3]),
                  "r"(bf[nt][0]), "r"(bf[nt][1]));
        }
}

template <int MODE>
__global__ void __launch_bounds__(256, 2)
mma_gemm_kernel() {
    extern __shared__ uint32_t smem[];  // [A0 | B0 | A1 | B1]

    const float* A  = g_a;                       // tf32 bits
    const float* Bt = MODE ? g_w2t : g_w1t;      // tf32 bits

    int tid = threadIdx.x, wid = tid >> 5, lane = tid & 31;
    int row0 = blockIdx.y * 128;
    int col0 = blockIdx.x * 128;
    int wm = (wid & 3) * 32;
    int wn = (wid >> 2) * 64;
    int gq = lane >> 2;
    int tq = lane & 3;

    uint32_t sbase = (uint32_t)__cvta_generic_to_shared(smem);

    // per-thread fixed load slots: 4 x 16B for A, 4 x 16B for B
    int lr[4], lc[4], lgrow[4];
#pragma unroll
    for (int i = 0; i < 4; i++) {
        int idx = tid + 256 * i;
        lr[i] = idx >> 3;
        lc[i] = (idx & 7) * 4;
        int grow = row0 + lr[i];
        lgrow[i] = (grow < NNODES) ? grow : (NNODES - 1);  // clamp: rows >= N never stored
    }

    float acc[2][8][4];
#pragma unroll
    for (int mt = 0; mt < 2; mt++)
#pragma unroll
        for (int nt = 0; nt < 8; nt++)
#pragma unroll
            for (int j = 0; j < 4; j++) acc[mt][nt][j] = 0.f;

    // prologue: issue chunk 0
    {
        uint32_t abuf = sbase, bbuf = sbase + SM_BUF * 4;
#pragma unroll
        for (int i = 0; i < 4; i++) {
            cp16(abuf + (uint32_t)(lr[i] * SMS + lc[i]) * 4, &A[(size_t)lgrow[i] * DIM + lc[i]]);
            cp16(bbuf + (uint32_t)(lr[i] * SMS + lc[i]) * 4, &Bt[(size_t)(col0 + lr[i]) * DIM + lc[i]]);
        }
        asm volatile("cp.async.commit_group;" ::: "memory");
    }

    for (int c = 0; c < 16; c++) {
        if (c < 15) {
            int kn = (c + 1) * 32;
            uint32_t abuf = sbase + ((c + 1) & 1) * 2 * SM_BUF * 4;
            uint32_t bbuf = abuf + SM_BUF * 4;
#pragma unroll
            for (int i = 0; i < 4; i++) {
                cp16(abuf + (uint32_t)(lr[i] * SMS + lc[i]) * 4,
                     &A[(size_t)lgrow[i] * DIM + kn + lc[i]]);
                cp16(bbuf + (uint32_t)(lr[i] * SMS + lc[i]) * 4,
                     &Bt[(size_t)(col0 + lr[i]) * DIM + kn + lc[i]]);
            }
            asm volatile("cp.async.commit_group;" ::: "memory");
            asm volatile("cp.async.wait_group 1;" ::: "memory");
        } else {
            asm volatile("cp.async.wait_group 0;" ::: "memory");
        }
        __syncthreads();

        const uint32_t* curA = smem + (c & 1) * 2 * SM_BUF;
        const uint32_t* curB = curA + SM_BUF;
        mma_ks(curA, curB, acc, 0,  wm, wn, gq, tq);
        mma_ks(curA, curB, acc, 8,  wm, wn, gq, tq);
        mma_ks(curA, curB, acc, 16, wm, wn, gq, tq);
        mma_ks(curA, curB, acc, 24, wm, wn, gq, tq);
        __syncthreads();
    }

    // ---- epilogue: fragments -> g_h ----
#pragma unroll
    for (int mt = 0; mt < 2; mt++) {
        int r0 = row0 + wm + mt * 16 + gq;
#pragma unroll
        for (int nt = 0; nt < 8; nt++) {
            int cc = col0 + wn + nt * 8 + tq * 2;
            if (r0 < NNODES)
                *(float2*)&g_h[(size_t)r0 * DIM + cc] =
                    make_float2(acc[mt][nt][0], acc[mt][nt][1]);
            if (r0 + 8 < NNODES)
                *(float2*)&g_h[(size_t)(r0 + 8) * DIM + cc] =
                    make_float2(acc[mt][nt][2], acc[mt][nt][3]);
        }
    }
}

// ---------------------------------------------------------------------------
// Launch 5: dinv + coalesced smem prefix scan of (deg-1) -> rowptr, cursor.
// ---------------------------------------------------------------------------
#define SCAN_T 1024
#define SCAN_CH ((NNODES + SCAN_T - 1) / SCAN_T)   // 20
#define SCAN_SMEM ((NNODES + SCAN_T) * 4)
__global__ void scan_dinv_kernel() {
    extern __shared__ int sm[];
    int* sums = sm + NNODES;
    int t = threadIdx.x;

    for (int i = t; i < NNODES; i += SCAN_T) {
        int dg = g_deg[i];
        g_dinv[i] = rsqrtf((float)dg);
        sm[i] = dg - 1;
    }
    __syncthreads();

    int base = t * SCAN_CH;
    int local = 0;
#pragma unroll
    for (int i = 0; i < SCAN_CH; i++) {
        int idx = base + i;
        if (idx < NNODES) local += sm[idx];
    }
    sums[t] = local;
    __syncthreads();
    for (int o = 1; o < SCAN_T; o <<= 1) {
        int v = (t >= o) ? sums[t - o] : 0;
        __syncthreads();
        sums[t] += v;
        __syncthreads();
    }
    int run = (t > 0) ? sums[t - 1] : 0;
#pragma unroll
    for (int i = 0; i < SCAN_CH; i++) {
        int idx = base + i;
        if (idx < NNODES) {
            int v = sm[idx];
            sm[idx] = run;
            run += v;
        }
    }
    __syncthreads();
    for (int i = t; i < NNODES; i += SCAN_T) {
        int r = sm[i];
        g_rowptr[i] = r;
        g_cursor[i] = r;
    }
    if (t == SCAN_T - 1) g_rowptr[NNODES] = sums[SCAN_T - 1];
}

// ---------------------------------------------------------------------------
// Launch 6: scatter edges into CSR (by dst), precomputing edge weight
// ---------------------------------------------------------------------------
__global__ void scatter_kernel() {
    int e = blockIdx.x * blockDim.x + threadIdx.x;
    if (e >= NEDGES) return;
    int s = g_src[e];
    int d = g_dst[e];
    int pos = atomicAdd(&g_cursor[d], 1);
    g_csr_src[pos] = s;
    g_csr_w[pos] = g_dinv[s] * g_dinv[d];
}

// ---------------------------------------------------------------------------
// Shared edge-accumulate body (fp32 exact):
//   acc = dinv[d]^2 * h[d,:] + sum_{e: dst=d} w_e * h[src_e,:]
// ---------------------------------------------------------------------------
__device__ __forceinline__ float4 agg_row(int d, int t) {
    const float4* __restrict__ h4 = (const float4*)g_h;
    float dv = g_dinv[d];
    float4 acc = h4[(size_t)d * 128 + t];
    float ws = dv * dv;
    acc.x *= ws; acc.y *= ws; acc.z *= ws; acc.w *= ws;

    int j   = g_rowptr[d];
    int end = g_rowptr[d + 1];
    for (; j + 4 <= end; j += 4) {
        int   s0 = g_csr_src[j],     s1 = g_csr_src[j + 1];
        int   s2 = g_csr_src[j + 2], s3 = g_csr_src[j + 3];
        float w0 = g_csr_w[j],       w1 = g_csr_w[j + 1];
        float w2 = g_csr_w[j + 2],   w3 = g_csr_w[j + 3];
        float4 v0 = h4[(size_t)s0 * 128 + t];
        float4 v1 = h4[(size_t)s1 * 128 + t];
        float4 v2 = h4[(size_t)s2 * 128 + t];
        float4 v3 = h4[(size_t)s3 * 128 + t];
        acc.x += v0.x * w0 + v1.x * w1 + v2.x * w2 + v3.x * w3;
        acc.y += v0.y * w0 + v1.y * w1 + v2.y * w2 + v3.y * w3;
        acc.z += v0.z * w0 + v1.z * w1 + v2.z * w2 + v3.z * w3;
        acc.w += v0.w * w0 + v1.w * w1 + v2.w * w2 + v3.w * w3;
    }
    for (; j < end; j++) {
        int   s = g_csr_src[j];
        float w = g_csr_w[j];
        float4 v = h4[(size_t)s * 128 + t];
        acc.x += v.x * w; acc.y += v.y * w;
        acc.z += v.z * w; acc.w += v.w * w;
    }
    return acc;
}

// Layer 1: agg + bias + relu + tf32(RNA) -> g_a (layer-2 GEMM A operand)
__global__ void __launch_bounds__(128)
agg_csr_tf32_kernel(const float* __restrict__ b1) {
    int d = blockIdx.x;
    int t = threadIdx.x;
    float4 acc = agg_row(d, t);
    float4 bb = ((const float4*)b1)[t];
    uint4 o = make_uint4(f2tf32(fmaxf(acc.x + bb.x, 0.f)),
                         f2tf32(fmaxf(acc.y + bb.y, 0.f)),
                         f2tf32(fmaxf(acc.z + bb.z, 0.f)),
                         f2tf32(fmaxf(acc.w + bb.w, 0.f)));
    ((uint4*)g_a)[(size_t)d * 128 + t] = o;
}

// Layer 2: plain fp32 aggregation -> g_a (consumed by maxpool)
__global__ void __launch_bounds__(128)
agg_csr_kernel() {
    int d = blockIdx.x;
    int t = threadIdx.x;
    ((float4*)g_a)[(size_t)d * 128 + t] = agg_row(d, t);
}

// ---------------------------------------------------------------------------
// Max pool: out[j] = max_i relu(a[i,j] + b2[j])   (out pre-zeroed in launch 1)
// ---------------------------------------------------------------------------
#define POOL_ROWS 100
__global__ void maxpool_kernel(const float* __restrict__ b2, float* __restrict__ out) {
    int col  = threadIdx.x;   // 512 threads
    int row0 = blockIdx.x * POOL_ROWS;
    float bb = b2[col];
    float m = 0.f;
#pragma unroll 4
    for (int r = 0; r < POOL_ROWS; r++) {
        int row = row0 + r;
        if (row >= NNODES) break;
        float v = g_a[(size_t)row * DIM + col] + bb;
        m = fmaxf(m, fmaxf(v, 0.f));
    }
    atomicMax((int*)out + col, __float_as_int(m));
}

// ---------------------------------------------------------------------------
extern "C" void kernel_launch(void* const* d_in, const int* in_sizes, int n_in,
                              void* d_out, int out_size) {
    const float* X  = (const float*)d_in[0];
    const void*  ei = d_in[1];
    // d_in[2] = edge_attr (unused by GCNConv)
    const float* W1 = (const float*)d_in[3];
    const float* b1 = (const float*)d_in[4];
    const float* W2 = (const float*)d_in[5];
    const float* b2 = (const float*)d_in[6];
    float* out = (float*)d_out;

    cudaFuncSetAttribute(scan_dinv_kernel,
                         cudaFuncAttributeMaxDynamicSharedMemorySize, SCAN_SMEM);
    cudaFuncSetAttribute(mma_gemm_kernel<0>,
                         cudaFuncAttributeMaxDynamicSharedMemorySize, GEMM_SMEM_BYTES);
    cudaFuncSetAttribute(mma_gemm_kernel<1>,
                         cudaFuncAttributeMaxDynamicSharedMemorySize, GEMM_SMEM_BYTES);

    dim3 gemm_grid(DIM / 128, (NNODES + 127) / 128);  // (4, 157)

    // 1: deg init | W transpose+tf32 | X->tf32 | out init | flag reset
    init_misc_kernel<<<DEGI_BLKS + TRAN_BLKS + XCNV_BLKS + 1, 256>>>(X, W1, W2, out);
    // 2: dtype sniff
    dtype_sniff_kernel<<<(NEDGES + 255) / 256, 256>>>((const int*)ei);
    // 3: edge convert + degree count
    convert_count_kernel<<<(2 * NEDGES + 255) / 256, 256>>>(ei);
    // 4: layer-1 GEMM (profiled slot)  h = tf32(X) @ W1
    mma_gemm_kernel<0><<<gemm_grid, 256, GEMM_SMEM_BYTES>>>();
    // 5: dinv + rowptr scan
    scan_dinv_kernel<<<1, SCAN_T, SCAN_SMEM>>>();
    // 6: CSR scatter
    scatter_kernel<<<(NEDGES + 255) / 256, 256>>>();
    // 7: layer-1 aggregation -> tf32(relu(a + b1))
    agg_csr_tf32_kernel<<<NNODES, 128>>>(b1);
    // 8: layer-2 GEMM  h = a @ W2
    mma_gemm_kernel<1><<<gemm_grid, 256, GEMM_SMEM_BYTES>>>();
    // 9: layer-2 aggregation (fp32)
    agg_csr_kernel<<<NNODES, 128>>>();
    // 10: global max pool over relu(a + b2)
    maxpool_kernel<<<(NNODES + POOL_ROWS - 1) / POOL_ROWS, DIM>>>(b2, out);
}

// round 14
// speedup vs baseline: 1.3733x; 1.0597x over previous
#include <cuda_runtime.h>
#include <cuda_fp16.h>
#include <cstdint>

#define NNODES 20000
#define NEDGES 320000
#define DIM    512

// Scratch (allocation-free rule: __device__ globals)
__device__ __half g_h[(size_t)NNODES * DIM];  // GEMM output h (fp16 storage)
__device__ float  g_a[(size_t)NNODES * DIM];  // GEMM A operand / agg result
__device__ float  g_dinv[NNODES];
__device__ int    g_deg[NNODES];
__device__ int    g_src[NEDGES];
__device__ int    g_dst[NEDGES];
__device__ int    g_is_i32;           // nonzero -> edge_index buffer is int32
__device__ int    g_rowptr[NNODES + 1];
__device__ int    g_cursor[NNODES];
__device__ int    g_csr_src[NEDGES];
__device__ float  g_csr_w[NEDGES];
__device__ float  g_w1t[DIM * DIM];   // W1^T, tf32 bits
__device__ float  g_w2t[DIM * DIM];   // W2^T, tf32 bits

__device__ __forceinline__ uint32_t f2tf32(float f) {
    uint32_t r;
    asm("cvt.rna.tf32.f32 %0, %1;" : "=r"(r) : "f"(f));
    return r;
}

// ---------------------------------------------------------------------------
// Launch 1 (fused): deg init | W transpose+tf32 | X->tf32 | out init + flag
// ---------------------------------------------------------------------------
#define DEGI_BLKS 79
#define TRAN_BLKS 512
#define XCNV_BLKS (NNODES * (DIM / 4) / 256)   // 10000
__global__ void init_misc_kernel(const float* __restrict__ X,
                                 const float* __restrict__ W1,
                                 const float* __restrict__ W2,
                                 float* __restrict__ out) {
    int b = blockIdx.x;
    int t = threadIdx.x;
    if (b < DEGI_BLKS) {
        int i = b * 256 + t;
        if (i < NNODES) g_deg[i] = 1;  // self-loop
        return;
    }
    if (b < DEGI_BLKS + TRAN_BLKS) {
        __shared__ float ts[32][33];
        int tile = b - DEGI_BLKS;
        const float* W = (tile >= 256) ? W2 : W1;
        float* o = (tile >= 256) ? g_w2t : g_w1t;
        int tl = tile & 255;
        int bx = (tl & 15) * 32, by = (tl >> 4) * 32;
        int r = t >> 3, c = (t & 7) * 4;
        float4 v = *(const float4*)&W[(size_t)(by + r) * DIM + bx + c];
        ts[r][c] = v.x; ts[r][c + 1] = v.y; ts[r][c + 2] = v.z; ts[r][c + 3] = v.w;
        __syncthreads();
        uint4 ov = make_uint4(f2tf32(ts[c][r]),     f2tf32(ts[c + 1][r]),
                              f2tf32(ts[c + 2][r]), f2tf32(ts[c + 3][r]));
        *(uint4*)&o[(size_t)(bx + r) * DIM + by + c] = ov;
        return;
    }
    if (b < DEGI_BLKS + TRAN_BLKS + XCNV_BLKS) {
        int idx = (b - DEGI_BLKS - TRAN_BLKS) * 256 + t;
        float4 v = ((const float4*)X)[idx];
        ((uint4*)g_a)[idx] =
            make_uint4(f2tf32(v.x), f2tf32(v.y), f2tf32(v.z), f2tf32(v.w));
        return;
    }
    out[t] = 0.0f;
    out[t + 256] = 0.0f;
    if (t == 0) g_is_i32 = 0;
}

// ---------------------------------------------------------------------------
// Launch 2: int32 vs int64 sniff (odd words all zero <=> int64)
// ---------------------------------------------------------------------------
__global__ void dtype_sniff_kernel(const int* __restrict__ ei32) {
    int i = blockIdx.x * blockDim.x + threadIdx.x;  // 0 .. E-1
    int acc = 0;
    if (i < NEDGES) acc = ei32[2 * i + 1];
#pragma unroll
    for (int o = 16; o > 0; o >>= 1) acc |= __shfl_xor_sync(0xffffffffu, acc, o);
    if ((threadIdx.x & 31) == 0 && acc != 0) atomicOr(&g_is_i32, 1);
}

// ---------------------------------------------------------------------------
// Launch 3: convert edge index to int32 + count in-degree
// ---------------------------------------------------------------------------
__global__ void convert_count_kernel(const void* __restrict__ ei) {
    int i = blockIdx.x * blockDim.x + threadIdx.x;  // 0 .. 2E-1
    if (i >= 2 * NEDGES) return;
    int v;
    if (g_is_i32) v = ((const int*)ei)[i];
    else          v = (int)((const long long*)ei)[i];
    if (i < NEDGES) {
        g_src[i] = v;
    } else {
        g_dst[i - NEDGES] = v;
        atomicAdd(&g_deg[v], 1);
    }
}

// ---------------------------------------------------------------------------
// Launch 4 (profiled slot): cp.async double-buffered tensor-core GEMM (tf32):
//   g_h[M,512] = g_a[M,512] @ Wt^T, epilogue stores fp16
// CTA 128x128, BK=32, 256 threads = 8 warps (4 M x 2 N), warp tile 32x64.
// ---------------------------------------------------------------------------
#define SMS 36                            // smem row stride (32 + 4 pad)
#define SM_BUF (128 * SMS)                // words per tile buffer
#define GEMM_SMEM_BYTES (4 * SM_BUF * 4)  // [A0 B0 A1 B1]

__device__ __forceinline__ void cp16(uint32_t dst, const void* src) {
    asm volatile("cp.async.cg.shared.global [%0], [%1], 16;"
                 :: "r"(dst), "l"(src));
}

__device__ __forceinline__ void mma_ks(const uint32_t* __restrict__ As_,
                                       const uint32_t* __restrict__ Bs_,
                                       float (&acc)[2][8][4],
                                       int k0, int wm, int wn, int gq, int tq) {
    uint32_t af[2][4], bf[8][2];
#pragma unroll
    for (int mt = 0; mt < 2; mt++) {
        int r = wm + mt * 16 + gq;
        af[mt][0] = As_[r * SMS + k0 + tq];
        af[mt][1] = As_[(r + 8) * SMS + k0 + tq];
        af[mt][2] = As_[r * SMS + k0 + tq + 4];
        af[mt][3] = As_[(r + 8) * SMS + k0 + tq + 4];
    }
#pragma unroll
    for (int nt = 0; nt < 8; nt++) {
        int n = wn + nt * 8 + gq;
        bf[nt][0] = Bs_[n * SMS + k0 + tq];
        bf[nt][1] = Bs_[n * SMS + k0 + tq + 4];
    }
#pragma unroll
    for (int mt = 0; mt < 2; mt++)
#pragma unroll
        for (int nt = 0; nt < 8; nt++) {
            asm volatile(
                "mma.sync.aligned.m16n8k8.row.col.f32.tf32.tf32.f32 "
                "{%0,%1,%2,%3}, {%4,%5,%6,%7}, {%8,%9}, {%0,%1,%2,%3};"
                : "+f"(acc[mt][nt][0]), "+f"(acc[mt][nt][1]),
                  "+f"(acc[mt][nt][2]), "+f"(acc[mt][nt][3])
                : "r"(af[mt][0]), "r"(af[mt][1]),
                  "r"(af[mt][2]), "r"(af[mt][3]),
                  "r"(bf[nt][0]), "r"(bf[nt][1]));
        }
}

template <int MODE>
__global__ void __launch_bounds__(256, 2)
mma_gemm_kernel() {
    extern __shared__ uint32_t smem[];  // [A0 | B0 | A1 | B1]

    const float* A  = g_a;                       // tf32 bits
    const float* Bt = MODE ? g_w2t : g_w1t;      // tf32 bits

    int tid = threadIdx.x, wid = tid >> 5, lane = tid & 31;
    int row0 = blockIdx.y * 128;
    int col0 = blockIdx.x * 128;
    int wm = (wid & 3) * 32;
    int wn = (wid >> 2) * 64;
    int gq = lane >> 2;
    int tq = lane & 3;

    uint32_t sbase = (uint32_t)__cvta_generic_to_shared(smem);

    int lr[4], lc[4], lgrow[4];
#pragma unroll
    for (int i = 0; i < 4; i++) {
        int idx = tid + 256 * i;
        lr[i] = idx >> 3;
        lc[i] = (idx & 7) * 4;
        int grow = row0 + lr[i];
        lgrow[i] = (grow < NNODES) ? grow : (NNODES - 1);  // clamp: rows >= N never stored
    }

    float acc[2][8][4];
#pragma unroll
    for (int mt = 0; mt < 2; mt++)
#pragma unroll
        for (int nt = 0; nt < 8; nt++)
#pragma unroll
            for (int j = 0; j < 4; j++) acc[mt][nt][j] = 0.f;

    // prologue: issue chunk 0
    {
        uint32_t abuf = sbase, bbuf = sbase + SM_BUF * 4;
#pragma unroll
        for (int i = 0; i < 4; i++) {
            cp16(abuf + (uint32_t)(lr[i] * SMS + lc[i]) * 4, &A[(size_t)lgrow[i] * DIM + lc[i]]);
            cp16(bbuf + (uint32_t)(lr[i] * SMS + lc[i]) * 4, &Bt[(size_t)(col0 + lr[i]) * DIM + lc[i]]);
        }
        asm volatile("cp.async.commit_group;" ::: "memory");
    }

    for (int c = 0; c < 16; c++) {
        if (c < 15) {
            int kn = (c + 1) * 32;
            uint32_t abuf = sbase + ((c + 1) & 1) * 2 * SM_BUF * 4;
            uint32_t bbuf = abuf + SM_BUF * 4;
#pragma unroll
            for (int i = 0; i < 4; i++) {
                cp16(abuf + (uint32_t)(lr[i] * SMS + lc[i]) * 4,
                     &A[(size_t)lgrow[i] * DIM + kn + lc[i]]);
                cp16(bbuf + (uint32_t)(lr[i] * SMS + lc[i]) * 4,
                     &Bt[(size_t)(col0 + lr[i]) * DIM + kn + lc[i]]);
            }
            asm volatile("cp.async.commit_group;" ::: "memory");
            asm volatile("cp.async.wait_group 1;" ::: "memory");
        } else {
            asm volatile("cp.async.wait_group 0;" ::: "memory");
        }
        __syncthreads();

        const uint32_t* curA = smem + (c & 1) * 2 * SM_BUF;
        const uint32_t* curB = curA + SM_BUF;
        mma_ks(curA, curB, acc, 0,  wm, wn, gq, tq);
        mma_ks(curA, curB, acc, 8,  wm, wn, gq, tq);
        mma_ks(curA, curB, acc, 16, wm, wn, gq, tq);
        mma_ks(curA, curB, acc, 24, wm, wn, gq, tq);
        __syncthreads();
    }

    // ---- epilogue: fragments -> g_h (fp16) ----
#pragma unroll
    for (int mt = 0; mt < 2; mt++) {
        int r0 = row0 + wm + mt * 16 + gq;
#pragma unroll
        for (int nt = 0; nt < 8; nt++) {
            int cc = col0 + wn + nt * 8 + tq * 2;
            if (r0 < NNODES)
                *(__half2*)&g_h[(size_t)r0 * DIM + cc] =
                    __floats2half2_rn(acc[mt][nt][0], acc[mt][nt][1]);
            if (r0 + 8 < NNODES)
                *(__half2*)&g_h[(size_t)(r0 + 8) * DIM + cc] =
                    __floats2half2_rn(acc[mt][nt][2], acc[mt][nt][3]);
        }
    }
}

// ---------------------------------------------------------------------------
// Launch 5: dinv + coalesced smem prefix scan of (deg-1) -> rowptr, cursor.
// ---------------------------------------------------------------------------
#define SCAN_T 1024
#define SCAN_CH ((NNODES + SCAN_T - 1) / SCAN_T)   // 20
#define SCAN_SMEM ((NNODES + SCAN_T) * 4)
__global__ void scan_dinv_kernel() {
    extern __shared__ int sm[];
    int* sums = sm + NNODES;
    int t = threadIdx.x;

    for (int i = t; i < NNODES; i += SCAN_T) {
        int dg = g_deg[i];
        g_dinv[i] = rsqrtf((float)dg);
        sm[i] = dg - 1;
    }
    __syncthreads();

    int base = t * SCAN_CH;
    int local = 0;
#pragma unroll
    for (int i = 0; i < SCAN_CH; i++) {
        int idx = base + i;
        if (idx < NNODES) local += sm[idx];
    }
    sums[t] = local;
    __syncthreads();
    for (int o = 1; o < SCAN_T; o <<= 1) {
        int v = (t >= o) ? sums[t - o] : 0;
        __syncthreads();
        sums[t] += v;
        __syncthreads();
    }
    int run = (t > 0) ? sums[t - 1] : 0;
#pragma unroll
    for (int i = 0; i < SCAN_CH; i++) {
        int idx = base + i;
        if (idx < NNODES) {
            int v = sm[idx];
            sm[idx] = run;
            run += v;
        }
    }
    __syncthreads();
    for (int i = t; i < NNODES; i += SCAN_T) {
        int r = sm[i];
        g_rowptr[i] = r;
        g_cursor[i] = r;
    }
    if (t == SCAN_T - 1) g_rowptr[NNODES] = sums[SCAN_T - 1];
}

// ---------------------------------------------------------------------------
// Launch 6: scatter edges into CSR (by dst), precomputing edge weight
// ---------------------------------------------------------------------------
__global__ void scatter_kernel() {
    int e = blockIdx.x * blockDim.x + threadIdx.x;
    if (e >= NEDGES) return;
    int s = g_src[e];
    int d = g_dst[e];
    int pos = atomicAdd(&g_cursor[d], 1);
    g_csr_src[pos] = s;
    g_csr_w[pos] = g_dinv[s] * g_dinv[d];
}

// ---------------------------------------------------------------------------
// Shared edge-accumulate body (fp32 accumulation over fp16 gathers):
//   acc = dinv[d]^2 * h[d,:] + sum_{e: dst=d} w_e * h[src_e,:]
// 128 threads; thread t owns cols [4t, 4t+4) = one uint2 (4 halfs).
// ---------------------------------------------------------------------------
__device__ __forceinline__ float4 h_load4(const uint2* __restrict__ hp, size_t idx) {
    uint2 raw = hp[idx];
    __half2 p0 = *(__half2*)&raw.x;
    __half2 p1 = *(__half2*)&raw.y;
    float2 f0 = __half22float2(p0);
    float2 f1 = __half22float2(p1);
    return make_float4(f0.x, f0.y, f1.x, f1.y);
}

__device__ __forceinline__ float4 agg_row(int d, int t) {
    const uint2* __restrict__ hp = (const uint2*)g_h;
    float dv = g_dinv[d];
    float4 acc = h_load4(hp, (size_t)d * 128 + t);
    float ws = dv * dv;
    acc.x *= ws; acc.y *= ws; acc.z *= ws; acc.w *= ws;

    int j   = g_rowptr[d];
    int end = g_rowptr[d + 1];
    for (; j + 4 <= end; j += 4) {
        int   s0 = g_csr_src[j],     s1 = g_csr_src[j + 1];
        int   s2 = g_csr_src[j + 2], s3 = g_csr_src[j + 3];
        float w0 = g_csr_w[j],       w1 = g_csr_w[j + 1];
        float w2 = g_csr_w[j + 2],   w3 = g_csr_w[j + 3];
        float4 v0 = h_load4(hp, (size_t)s0 * 128 + t);
        float4 v1 = h_load4(hp, (size_t)s1 * 128 + t);
        float4 v2 = h_load4(hp, (size_t)s2 * 128 + t);
        float4 v3 = h_load4(hp, (size_t)s3 * 128 + t);
        acc.x += v0.x * w0 + v1.x * w1 + v2.x * w2 + v3.x * w3;
        acc.y += v0.y * w0 + v1.y * w1 + v2.y * w2 + v3.y * w3;
        acc.z += v0.z * w0 + v1.z * w1 + v2.z * w2 + v3.z * w3;
        acc.w += v0.w * w0 + v1.w * w1 + v2.w * w2 + v3.w * w3;
    }
    for (; j < end; j++) {
        int   s = g_csr_src[j];
        float w = g_csr_w[j];
        float4 v = h_load4(hp, (size_t)s * 128 + t);
        acc.x += v.x * w; acc.y += v.y * w;
        acc.z += v.z * w; acc.w += v.w * w;
    }
    return acc;
}

// Layer 1: agg + bias + relu + tf32(RNA) -> g_a (layer-2 GEMM A operand)
__global__ void __launch_bounds__(128)
agg_csr_tf32_kernel(const float* __restrict__ b1) {
    int d = blockIdx.x;
    int t = threadIdx.x;
    float4 acc = agg_row(d, t);
    float4 bb = ((const float4*)b1)[t];
    uint4 o = make_uint4(f2tf32(fmaxf(acc.x + bb.x, 0.f)),
                         f2tf32(fmaxf(acc.y + bb.y, 0.f)),
                         f2tf32(fmaxf(acc.z + bb.z, 0.f)),
                         f2tf32(fmaxf(acc.w + bb.w, 0.f)));
    ((uint4*)g_a)[(size_t)d * 128 + t] = o;
}

// Layer 2: plain fp32 aggregation -> g_a (consumed by maxpool)
__global__ void __launch_bounds__(128)
agg_csr_kernel() {
    int d = blockIdx.x;
    int t = threadIdx.x;
    ((float4*)g_a)[(size_t)d * 128 + t] = agg_row(d, t);
}

// ---------------------------------------------------------------------------
// Max pool: out[j] = max_i relu(a[i,j] + b2[j])   (out pre-zeroed in launch 1)
// ---------------------------------------------------------------------------
#define POOL_ROWS 100
__global__ void maxpool_kernel(const float* __restrict__ b2, float* __restrict__ out) {
    int col  = threadIdx.x;   // 512 threads
    int row0 = blockIdx.x * POOL_ROWS;
    float bb = b2[col];
    float m = 0.f;
#pragma unroll 4
    for (int r = 0; r < POOL_ROWS; r++) {
        int row = row0 + r;
        if (row >= NNODES) break;
        float v = g_a[(size_t)row * DIM + col] + bb;
        m = fmaxf(m, fmaxf(v, 0.f));
    }
    atomicMax((int*)out + col, __float_as_int(m));
}

// ---------------------------------------------------------------------------
extern "C" void kernel_launch(void* const* d_in, const int* in_sizes, int n_in,
                              void* d_out, int out_size) {
    const float* X  = (const float*)d_in[0];
    const void*  ei = d_in[1];
    // d_in[2] = edge_attr (unused by GCNConv)
    const float* W1 = (const float*)d_in[3];
    const float* b1 = (const float*)d_in[4];
    const float* W2 = (const float*)d_in[5];
    const float* b2 = (const float*)d_in[6];
    float* out = (float*)d_out;

    cudaFuncSetAttribute(scan_dinv_kernel,
                         cudaFuncAttributeMaxDynamicSharedMemorySize, SCAN_SMEM);
    cudaFuncSetAttribute(mma_gemm_kernel<0>,
                         cudaFuncAttributeMaxDynamicSharedMemorySize, GEMM_SMEM_BYTES);
    cudaFuncSetAttribute(mma_gemm_kernel<1>,
                         cudaFuncAttributeMaxDynamicSharedMemorySize, GEMM_SMEM_BYTES);

    dim3 gemm_grid(DIM / 128, (NNODES + 127) / 128);  // (4, 157)

    // 1: deg init | W transpose+tf32 | X->tf32 | out init | flag reset
    init_misc_kernel<<<DEGI_BLKS + TRAN_BLKS + XCNV_BLKS + 1, 256>>>(X, W1, W2, out);
    // 2: dtype sniff
    dtype_sniff_kernel<<<(NEDGES + 255) / 256, 256>>>((const int*)ei);
    // 3: edge convert + degree count
    convert_count_kernel<<<(2 * NEDGES + 255) / 256, 256>>>(ei);
    // 4: layer-1 GEMM (profiled slot)  h = tf32(X) @ W1  -> fp16
    mma_gemm_kernel<0><<<gemm_grid, 256, GEMM_SMEM_BYTES>>>();
    // 5: dinv + rowptr scan
    scan_dinv_kernel<<<1, SCAN_T, SCAN_SMEM>>>();
    // 6: CSR scatter
    scatter_kernel<<<(NEDGES + 255) / 256, 256>>>();
    // 7: layer-1 aggregation -> tf32(relu(a + b1))
    agg_csr_tf32_kernel<<<NNODES, 128>>>(b1);
    // 8: layer-2 GEMM  h = a @ W2  -> fp16
    mma_gemm_kernel<1><<<gemm_grid, 256, GEMM_SMEM_BYTES>>>();
    // 9: layer-2 aggregation (fp32)
    agg_csr_kernel<<<NNODES, 128>>>();
    // 10: global max pool over relu(a + b2)
    maxpool_kernel<<<(NNODES + POOL_ROWS - 1) / POOL_ROWS, DIM>>>(b2, out);
}

// round 15
// speedup vs baseline: 1.7527x; 1.2763x over previous
#include <cuda_runtime.h>
#include <cuda_fp16.h>
#include <cstdint>

#define NNODES 20000
#define NEDGES 320000
#define DIM    512

// Scratch (allocation-free rule: __device__ globals)
__device__ __half g_h[(size_t)NNODES * DIM];  // GEMM output h (fp16 storage)
__device__ __half g_a[(size_t)NNODES * DIM];  // GEMM A operand (fp16)
__device__ float  g_agg[(size_t)NNODES * DIM]; // layer-2 agg result (fp32)
__device__ float  g_dinv[NNODES];
__device__ int    g_deg[NNODES];
__device__ int    g_src[NEDGES];
__device__ int    g_dst[NEDGES];
__device__ int    g_is_i32;           // nonzero -> edge_index buffer is int32
__device__ int    g_rowptr[NNODES + 1];
__device__ int    g_cursor[NNODES];
__device__ int    g_csr_src[NEDGES];
__device__ float  g_csr_w[NEDGES];
__device__ __half g_w1t[DIM * DIM];   // W1^T, fp16
__device__ __half g_w2t[DIM * DIM];   // W2^T, fp16

// ---------------------------------------------------------------------------
// Launch 1 (fused): deg init | W transpose+fp16 | X->fp16 | out init + flag
// ---------------------------------------------------------------------------
#define DEGI_BLKS 79
#define TRAN_BLKS 512
#define XCNV_BLKS (NNODES * (DIM / 4) / 256)   // 10000
__global__ void init_misc_kernel(const float* __restrict__ X,
                                 const float* __restrict__ W1,
                                 const float* __restrict__ W2,
                                 float* __restrict__ out) {
    int b = blockIdx.x;
    int t = threadIdx.x;
    if (b < DEGI_BLKS) {
        int i = b * 256 + t;
        if (i < NNODES) g_deg[i] = 1;  // self-loop
        return;
    }
    if (b < DEGI_BLKS + TRAN_BLKS) {
        __shared__ float ts[32][33];
        int tile = b - DEGI_BLKS;
        const float* W = (tile >= 256) ? W2 : W1;
        __half* o = (tile >= 256) ? g_w2t : g_w1t;
        int tl = tile & 255;
        int bx = (tl & 15) * 32, by = (tl >> 4) * 32;
        int r = t >> 3, c = (t & 7) * 4;
        float4 v = *(const float4*)&W[(size_t)(by + r) * DIM + bx + c];
        ts[r][c] = v.x; ts[r][c + 1] = v.y; ts[r][c + 2] = v.z; ts[r][c + 3] = v.w;
        __syncthreads();
        __half2 h0 = __floats2half2_rn(ts[c][r], ts[c + 1][r]);
        __half2 h1 = __floats2half2_rn(ts[c + 2][r], ts[c + 3][r]);
        uint2 ov = make_uint2(*(uint32_t*)&h0, *(uint32_t*)&h1);
        *(uint2*)&o[(size_t)(bx + r) * DIM + by + c] = ov;
        return;
    }
    if (b < DEGI_BLKS + TRAN_BLKS + XCNV_BLKS) {
        int idx = (b - DEGI_BLKS - TRAN_BLKS) * 256 + t;
        float4 v = ((const float4*)X)[idx];
        __half2 h0 = __floats2half2_rn(v.x, v.y);
        __half2 h1 = __floats2half2_rn(v.z, v.w);
        ((uint2*)g_a)[idx] = make_uint2(*(uint32_t*)&h0, *(uint32_t*)&h1);
        return;
    }
    out[t] = 0.0f;
    out[t + 256] = 0.0f;
    if (t == 0) g_is_i32 = 0;
}

// ---------------------------------------------------------------------------
// Launch 2: int32 vs int64 sniff (odd words all zero <=> int64)
// ---------------------------------------------------------------------------
__global__ void dtype_sniff_kernel(const int* __restrict__ ei32) {
    int i = blockIdx.x * blockDim.x + threadIdx.x;  // 0 .. E-1
    int acc = 0;
    if (i < NEDGES) acc = ei32[2 * i + 1];
#pragma unroll
    for (int o = 16; o > 0; o >>= 1) acc |= __shfl_xor_sync(0xffffffffu, acc, o);
    if ((threadIdx.x & 31) == 0 && acc != 0) atomicOr(&g_is_i32, 1);
}

// ---------------------------------------------------------------------------
// Launch 3: convert edge index to int32 + count in-degree
// ---------------------------------------------------------------------------
__global__ void convert_count_kernel(const void* __restrict__ ei) {
    int i = blockIdx.x * blockDim.x + threadIdx.x;  // 0 .. 2E-1
    if (i >= 2 * NEDGES) return;
    int v;
    if (g_is_i32) v = ((const int*)ei)[i];
    else          v = (int)((const long long*)ei)[i];
    if (i < NEDGES) {
        g_src[i] = v;
    } else {
        g_dst[i - NEDGES] = v;
        atomicAdd(&g_deg[v], 1);
    }
}

// ---------------------------------------------------------------------------
// Launch 4 (profiled slot): cp.async double-buffered fp16 HMMA GEMM:
//   g_h[M,512] = g_a[M,512] @ Wt^T (fp16 in, fp32 acc, fp16 out)
// CTA 128x128, BK=32, 256 threads = 8 warps (4 M x 2 N), warp tile 32x64.
// mma.m16n8k16: each b32 reg = 2 consecutive halfs along K.
// ---------------------------------------------------------------------------
#define SMSW 20                            // smem row stride in words (16 + 4 pad)
#define SM_BUF (128 * SMSW)                // words per tile buffer
#define GEMM_SMEM_BYTES (4 * SM_BUF * 4)   // [A0 B0 A1 B1] = 40 KB

__device__ __forceinline__ void cp16(uint32_t dst, const void* src) {
    asm volatile("cp.async.cg.shared.global [%0], [%1], 16;"
                 :: "r"(dst), "l"(src));
}

// one k-step (K=16): k0w = word offset (0 or 8) within the 32-half chunk
__device__ __forceinline__ void mma_ks(const uint32_t* __restrict__ As_,
                                       const uint32_t* __restrict__ Bs_,
                                       float (&acc)[2][8][4],
                                       int k0w, int wm, int wn, int gq, int tq) {
    uint32_t af[2][4], bf[8][2];
#pragma unroll
    for (int mt = 0; mt < 2; mt++) {
        int r = wm + mt * 16 + gq;
        af[mt][0] = As_[r * SMSW + k0w + tq];
        af[mt][1] = As_[(r + 8) * SMSW + k0w + tq];
        af[mt][2] = As_[r * SMSW + k0w + tq + 4];
        af[mt][3] = As_[(r + 8) * SMSW + k0w + tq + 4];
    }
#pragma unroll
    for (int nt = 0; nt < 8; nt++) {
        int n = wn + nt * 8 + gq;
        bf[nt][0] = Bs_[n * SMSW + k0w + tq];
        bf[nt][1] = Bs_[n * SMSW + k0w + tq + 4];
    }
#pragma unroll
    for (int mt = 0; mt < 2; mt++)
#pragma unroll
        for (int nt = 0; nt < 8; nt++) {
            asm volatile(
                "mma.sync.aligned.m16n8k16.row.col.f32.f16.f16.f32 "
                "{%0,%1,%2,%3}, {%4,%5,%6,%7}, {%8,%9}, {%0,%1,%2,%3};"
                : "+f"(acc[mt][nt][0]), "+f"(acc[mt][nt][1]),
                  "+f"(acc[mt][nt][2]), "+f"(acc[mt][nt][3])
                : "r"(af[mt][0]), "r"(af[mt][1]),
                  "r"(af[mt][2]), "r"(af[mt][3]),
                  "r"(bf[nt][0]), "r"(bf[nt][1]));
        }
}

template <int MODE>
__global__ void __launch_bounds__(256, 2)
mma_gemm_kernel() {
    extern __shared__ uint32_t smem[];  // [A0 | B0 | A1 | B1]

    const __half* A  = g_a;
    const __half* Bt = MODE ? g_w2t : g_w1t;

    int tid = threadIdx.x, wid = tid >> 5, lane = tid & 31;
    int row0 = blockIdx.y * 128;
    int col0 = blockIdx.x * 128;
    int wm = (wid & 3) * 32;
    int wn = (wid >> 2) * 64;
    int gq = lane >> 2;
    int tq = lane & 3;

    uint32_t sbase = (uint32_t)__cvta_generic_to_shared(smem);

    // per-thread fixed load slots: 2 x 16B (=8 halfs) for A, 2 for B
    // tile = 128 rows x 32 halfs = 512 x 16B
    int lr[2], lw[2], lh[2], lgrow[2];
#pragma unroll
    for (int i = 0; i < 2; i++) {
        int idx = tid + 256 * i;          // 0..511
        lr[i] = idx >> 2;                 // row 0..127
        lw[i] = (idx & 3) * 4;            // word offset in row: 0,4,8,12
        lh[i] = (idx & 3) * 8;            // half offset in row: 0,8,16,24
        int grow = row0 + lr[i];
        lgrow[i] = (grow < NNODES) ? grow : (NNODES - 1);  // clamp: rows >= N never stored
    }

    float acc[2][8][4];
#pragma unroll
    for (int mt = 0; mt < 2; mt++)
#pragma unroll
        for (int nt = 0; nt < 8; nt++)
#pragma unroll
            for (int j = 0; j < 4; j++) acc[mt][nt][j] = 0.f;

    // prologue: issue chunk 0
    {
        uint32_t abuf = sbase, bbuf = sbase + SM_BUF * 4;
#pragma unroll
        for (int i = 0; i < 2; i++) {
            cp16(abuf + (uint32_t)(lr[i] * SMSW + lw[i]) * 4, &A[(size_t)lgrow[i] * DIM + lh[i]]);
            cp16(bbuf + (uint32_t)(lr[i] * SMSW + lw[i]) * 4, &Bt[(size_t)(col0 + lr[i]) * DIM + lh[i]]);
        }
        asm volatile("cp.async.commit_group;" ::: "memory");
    }

    for (int c = 0; c < 16; c++) {
        if (c < 15) {
            int kn = (c + 1) * 32;
            uint32_t abuf = sbase + ((c + 1) & 1) * 2 * SM_BUF * 4;
            uint32_t bbuf = abuf + SM_BUF * 4;
#pragma unroll
            for (int i = 0; i < 2; i++) {
                cp16(abuf + (uint32_t)(lr[i] * SMSW + lw[i]) * 4,
                     &A[(size_t)lgrow[i] * DIM + kn + lh[i]]);
                cp16(bbuf + (uint32_t)(lr[i] * SMSW + lw[i]) * 4,
                     &Bt[(size_t)(col0 + lr[i]) * DIM + kn + lh[i]]);
            }
            asm volatile("cp.async.commit_group;" ::: "memory");
            asm volatile("cp.async.wait_group 1;" ::: "memory");
        } else {
            asm volatile("cp.async.wait_group 0;" ::: "memory");
        }
        __syncthreads();

        const uint32_t* curA = smem + (c & 1) * 2 * SM_BUF;
        const uint32_t* curB = curA + SM_BUF;
        mma_ks(curA, curB, acc, 0, wm, wn, gq, tq);   // K 0..15
        mma_ks(curA, curB, acc, 8, wm, wn, gq, tq);   // K 16..31
        __syncthreads();
    }

    // ---- epilogue: fragments -> g_h (fp16) ----
#pragma unroll
    for (int mt = 0; mt < 2; mt++) {
        int r0 = row0 + wm + mt * 16 + gq;
#pragma unroll
        for (int nt = 0; nt < 8; nt++) {
            int cc = col0 + wn + nt * 8 + tq * 2;
            if (r0 < NNODES)
                *(__half2*)&g_h[(size_t)r0 * DIM + cc] =
                    __floats2half2_rn(acc[mt][nt][0], acc[mt][nt][1]);
            if (r0 + 8 < NNODES)
                *(__half2*)&g_h[(size_t)(r0 + 8) * DIM + cc] =
                    __floats2half2_rn(acc[mt][nt][2], acc[mt][nt][3]);
        }
    }
}

// ---------------------------------------------------------------------------
// Launch 5: dinv + coalesced smem prefix scan of (deg-1) -> rowptr, cursor.
// ---------------------------------------------------------------------------
#define SCAN_T 1024
#define SCAN_CH ((NNODES + SCAN_T - 1) / SCAN_T)   // 20
#define SCAN_SMEM ((NNODES + SCAN_T) * 4)
__global__ void scan_dinv_kernel() {
    extern __shared__ int sm[];
    int* sums = sm + NNODES;
    int t = threadIdx.x;

    for (int i = t; i < NNODES; i += SCAN_T) {
        int dg = g_deg[i];
        g_dinv[i] = rsqrtf((float)dg);
        sm[i] = dg - 1;
    }
    __syncthreads();

    int base = t * SCAN_CH;
    int local = 0;
#pragma unroll
    for (int i = 0; i < SCAN_CH; i++) {
        int idx = base + i;
        if (idx < NNODES) local += sm[idx];
    }
    sums[t] = local;
    __syncthreads();
    for (int o = 1; o < SCAN_T; o <<= 1) {
        int v = (t >= o) ? sums[t - o] : 0;
        __syncthreads();
        sums[t] += v;
        __syncthreads();
    }
    int run = (t > 0) ? sums[t - 1] : 0;
#pragma unroll
    for (int i = 0; i < SCAN_CH; i++) {
        int idx = base + i;
        if (idx < NNODES) {
            int v = sm[idx];
            sm[idx] = run;
            run += v;
        }
    }
    __syncthreads();
    for (int i = t; i < NNODES; i += SCAN_T) {
        int r = sm[i];
        g_rowptr[i] = r;
        g_cursor[i] = r;
    }
    if (t == SCAN_T - 1) g_rowptr[NNODES] = sums[SCAN_T - 1];
}

// ---------------------------------------------------------------------------
// Launch 6: scatter edges into CSR (by dst), precomputing edge weight
// ---------------------------------------------------------------------------
__global__ void scatter_kernel() {
    int e = blockIdx.x * blockDim.x + threadIdx.x;
    if (e >= NEDGES) return;
    int s = g_src[e];
    int d = g_dst[e];
    int pos = atomicAdd(&g_cursor[d], 1);
    g_csr_src[pos] = s;
    g_csr_w[pos] = g_dinv[s] * g_dinv[d];
}

// ---------------------------------------------------------------------------
// Shared edge-accumulate body (fp32 accumulation over fp16 gathers):
//   acc = dinv[d]^2 * h[d,:] + sum_{e: dst=d} w_e * h[src_e,:]
// 128 threads; thread t owns cols [4t, 4t+4) = one uint2 (4 halfs).
// ---------------------------------------------------------------------------
__device__ __forceinline__ float4 h_load4(const uint2* __restrict__ hp, size_t idx) {
    uint2 raw = hp[idx];
    float2 f0 = __half22float2(*(__half2*)&raw.x);
    float2 f1 = __half22float2(*(__half2*)&raw.y);
    return make_float4(f0.x, f0.y, f1.x, f1.y);
}

__device__ __forceinline__ float4 agg_row(int d, int t) {
    const uint2* __restrict__ hp = (const uint2*)g_h;
    float dv = g_dinv[d];
    float4 acc = h_load4(hp, (size_t)d * 128 + t);
    float ws = dv * dv;
    acc.x *= ws; acc.y *= ws; acc.z *= ws; acc.w *= ws;

    int j   = g_rowptr[d];
    int end = g_rowptr[d + 1];
    for (; j + 4 <= end; j += 4) {
        int   s0 = g_csr_src[j],     s1 = g_csr_src[j + 1];
        int   s2 = g_csr_src[j + 2], s3 = g_csr_src[j + 3];
        float w0 = g_csr_w[j],       w1 = g_csr_w[j + 1];
        float w2 = g_csr_w[j + 2],   w3 = g_csr_w[j + 3];
        float4 v0 = h_load4(hp, (size_t)s0 * 128 + t);
        float4 v1 = h_load4(hp, (size_t)s1 * 128 + t);
        float4 v2 = h_load4(hp, (size_t)s2 * 128 + t);
        float4 v3 = h_load4(hp, (size_t)s3 * 128 + t);
        acc.x += v0.x * w0 + v1.x * w1 + v2.x * w2 + v3.x * w3;
        acc.y += v0.y * w0 + v1.y * w1 + v2.y * w2 + v3.y * w3;
        acc.z += v0.z * w0 + v1.z * w1 + v2.z * w2 + v3.z * w3;
        acc.w += v0.w * w0 + v1.w * w1 + v2.w * w2 + v3.w * w3;
    }
    for (; j < end; j++) {
        int   s = g_csr_src[j];
        float w = g_csr_w[j];
        float4 v = h_load4(hp, (size_t)s * 128 + t);
        acc.x += v.x * w; acc.y += v.y * w;
        acc.z += v.z * w; acc.w += v.w * w;
    }
    return acc;
}

// Layer 1: agg + bias + relu -> fp16 g_a (layer-2 GEMM A operand)
__global__ void __launch_bounds__(128)
agg_csr_half_kernel(const float* __restrict__ b1) {
    int d = blockIdx.x;
    int t = threadIdx.x;
    float4 acc = agg_row(d, t);
    float4 bb = ((const float4*)b1)[t];
    __half2 h0 = __floats2half2_rn(fmaxf(acc.x + bb.x, 0.f), fmaxf(acc.y + bb.y, 0.f));
    __half2 h1 = __floats2half2_rn(fmaxf(acc.z + bb.z, 0.f), fmaxf(acc.w + bb.w, 0.f));
    ((uint2*)g_a)[(size_t)d * 128 + t] = make_uint2(*(uint32_t*)&h0, *(uint32_t*)&h1);
}

// Layer 2: plain fp32 aggregation -> g_agg (consumed by maxpool)
__global__ void __launch_bounds__(128)
agg_csr_kernel() {
    int d = blockIdx.x;
    int t = threadIdx.x;
    ((float4*)g_agg)[(size_t)d * 128 + t] = agg_row(d, t);
}

// ---------------------------------------------------------------------------
// Max pool: out[j] = max_i relu(agg[i,j] + b2[j])  (out pre-zeroed in launch 1)
// ---------------------------------------------------------------------------
#define POOL_ROWS 100
__global__ void maxpool_kernel(const float* __restrict__ b2, float* __restrict__ out) {
    int col  = threadIdx.x;   // 512 threads
    int row0 = blockIdx.x * POOL_ROWS;
    float bb = b2[col];
    float m = 0.f;
#pragma unroll 4
    for (int r = 0; r < POOL_ROWS; r++) {
        int row = row0 + r;
        if (row >= NNODES) break;
        float v = g_agg[(size_t)row * DIM + col] + bb;
        m = fmaxf(m, fmaxf(v, 0.f));
    }
    atomicMax((int*)out + col, __float_as_int(m));
}

// ---------------------------------------------------------------------------
extern "C" void kernel_launch(void* const* d_in, const int* in_sizes, int n_in,
                              void* d_out, int out_size) {
    const float* X  = (const float*)d_in[0];
    const void*  ei = d_in[1];
    // d_in[2] = edge_attr (unused by GCNConv)
    const float* W1 = (const float*)d_in[3];
    const float* b1 = (const float*)d_in[4];
    const float* W2 = (const float*)d_in[5];
    const float* b2 = (const float*)d_in[6];
    float* out = (float*)d_out;

    cudaFuncSetAttribute(scan_dinv_kernel,
                         cudaFuncAttributeMaxDynamicSharedMemorySize, SCAN_SMEM);
    cudaFuncSetAttribute(mma_gemm_kernel<0>,
                         cudaFuncAttributeMaxDynamicSharedMemorySize, GEMM_SMEM_BYTES);
    cudaFuncSetAttribute(mma_gemm_kernel<1>,
                         cudaFuncAttributeMaxDynamicSharedMemorySize, GEMM_SMEM_BYTES);

    dim3 gemm_grid(DIM / 128, (NNODES + 127) / 128);  // (4, 157)

    // 1: deg init | W transpose+fp16 | X->fp16 | out init | flag reset
    init_misc_kernel<<<DEGI_BLKS + TRAN_BLKS + XCNV_BLKS + 1, 256>>>(X, W1, W2, out);
    // 2: dtype sniff
    dtype_sniff_kernel<<<(NEDGES + 255) / 256, 256>>>((const int*)ei);
    // 3: edge convert + degree count
    convert_count_kernel<<<(2 * NEDGES + 255) / 256, 256>>>(ei);
    // 4: layer-1 GEMM (profiled slot)  h = fp16(X) @ W1  (fp32 acc) -> fp16
    mma_gemm_kernel<0><<<gemm_grid, 256, GEMM_SMEM_BYTES>>>();
    // 5: dinv + rowptr scan
    scan_dinv_kernel<<<1, SCAN_T, SCAN_SMEM>>>();
    // 6: CSR scatter
    scatter_kernel<<<(NEDGES + 255) / 256, 256>>>();
    // 7: layer-1 aggregation -> fp16(relu(a + b1))
    agg_csr_half_kernel<<<NNODES, 128>>>(b1);
    // 8: layer-2 GEMM  h = a @ W2 -> fp16
    mma_gemm_kernel<1><<<gemm_grid, 256, GEMM_SMEM_BYTES>>>();
    // 9: layer-2 aggregation (fp32)
    agg_csr_kernel<<<NNODES, 128>>>();
    // 10: global max pool over relu(agg + b2)
    maxpool_kernel<<<(NNODES + POOL_ROWS - 1) / POOL_ROWS, DIM>>>(b2, out);
}

// round 16
// speedup vs baseline: 1.7638x; 1.0063x over previous
#include <cuda_runtime.h>
#include <cuda_fp16.h>
#include <cstdint>

#define NNODES 20000
#define NEDGES 320000
#define DIM    512

// Scratch (allocation-free rule: __device__ globals)
__device__ __half g_h[(size_t)NNODES * DIM];  // GEMM output h (fp16 storage)
__device__ __half g_a[(size_t)NNODES * DIM];  // GEMM A operand (fp16)
__device__ float  g_agg[(size_t)NNODES * DIM]; // layer-2 agg result (fp32)
__device__ float  g_dinv[NNODES];
__device__ int    g_deg[NNODES];
__device__ int    g_src[NEDGES];
__device__ int    g_dst[NEDGES];
__device__ int    g_is_i32;           // nonzero -> edge_index buffer is int32
__device__ int    g_rowptr[NNODES + 1];
__device__ int    g_cursor[NNODES];
__device__ int    g_csr_src[NEDGES];
__device__ float  g_csr_w[NEDGES];
__device__ __half g_w1t[DIM * DIM];   // W1^T, fp16
__device__ __half g_w2t[DIM * DIM];   // W2^T, fp16

// ---------------------------------------------------------------------------
// Launch 1 (fused): deg init | W transpose+fp16 | X->fp16 | out init + flag
// ---------------------------------------------------------------------------
#define DEGI_BLKS 79
#define TRAN_BLKS 512
#define XCNV_BLKS (NNODES * (DIM / 4) / 256)   // 10000
__global__ void init_misc_kernel(const float* __restrict__ X,
                                 const float* __restrict__ W1,
                                 const float* __restrict__ W2,
                                 float* __restrict__ out) {
    int b = blockIdx.x;
    int t = threadIdx.x;
    if (b < DEGI_BLKS) {
        int i = b * 256 + t;
        if (i < NNODES) g_deg[i] = 1;  // self-loop
        return;
    }
    if (b < DEGI_BLKS + TRAN_BLKS) {
        __shared__ float ts[32][33];
        int tile = b - DEGI_BLKS;
        const float* W = (tile >= 256) ? W2 : W1;
        __half* o = (tile >= 256) ? g_w2t : g_w1t;
        int tl = tile & 255;
        int bx = (tl & 15) * 32, by = (tl >> 4) * 32;
        int r = t >> 3, c = (t & 7) * 4;
        float4 v = *(const float4*)&W[(size_t)(by + r) * DIM + bx + c];
        ts[r][c] = v.x; ts[r][c + 1] = v.y; ts[r][c + 2] = v.z; ts[r][c + 3] = v.w;
        __syncthreads();
        __half2 h0 = __floats2half2_rn(ts[c][r], ts[c + 1][r]);
        __half2 h1 = __floats2half2_rn(ts[c + 2][r], ts[c + 3][r]);
        uint2 ov = make_uint2(*(uint32_t*)&h0, *(uint32_t*)&h1);
        *(uint2*)&o[(size_t)(bx + r) * DIM + by + c] = ov;
        return;
    }
    if (b < DEGI_BLKS + TRAN_BLKS + XCNV_BLKS) {
        int idx = (b - DEGI_BLKS - TRAN_BLKS) * 256 + t;
        float4 v = ((const float4*)X)[idx];
        __half2 h0 = __floats2half2_rn(v.x, v.y);
        __half2 h1 = __floats2half2_rn(v.z, v.w);
        ((uint2*)g_a)[idx] = make_uint2(*(uint32_t*)&h0, *(uint32_t*)&h1);
        return;
    }
    out[t] = 0.0f;
    out[t + 256] = 0.0f;
    if (t == 0) g_is_i32 = 0;
}

// ---------------------------------------------------------------------------
// Launch 2: int32 vs int64 sniff (odd words all zero <=> int64)
// ---------------------------------------------------------------------------
__global__ void dtype_sniff_kernel(const int* __restrict__ ei32) {
    int i = blockIdx.x * blockDim.x + threadIdx.x;  // 0 .. E-1
    int acc = 0;
    if (i < NEDGES) acc = ei32[2 * i + 1];
#pragma unroll
    for (int o = 16; o > 0; o >>= 1) acc |= __shfl_xor_sync(0xffffffffu, acc, o);
    if ((threadIdx.x & 31) == 0 && acc != 0) atomicOr(&g_is_i32, 1);
}

// ---------------------------------------------------------------------------
// Launch 3: convert edge index to int32 + count in-degree
// ---------------------------------------------------------------------------
__global__ void convert_count_kernel(const void* __restrict__ ei) {
    int i = blockIdx.x * blockDim.x + threadIdx.x;  // 0 .. 2E-1
    if (i >= 2 * NEDGES) return;
    int v;
    if (g_is_i32) v = ((const int*)ei)[i];
    else          v = (int)((const long long*)ei)[i];
    if (i < NEDGES) {
        g_src[i] = v;
    } else {
        g_dst[i - NEDGES] = v;
        atomicAdd(&g_deg[v], 1);
    }
}

// ---------------------------------------------------------------------------
// Launch 4 (profiled slot): 3-stage cp.async pipelined fp16 HMMA GEMM:
//   g_h[M,512] = g_a[M,512] @ Wt^T (fp16 in, fp32 acc, fp16 out)
// CTA 128x128, BK=32, 256 threads = 8 warps (4 M x 2 N), warp tile 32x64.
// ONE __syncthreads per chunk (multistage pattern).
// ---------------------------------------------------------------------------
#define SMSW 20                            // smem row stride in words (16 + 4 pad)
#define SM_BUF (128 * SMSW)                // words per A or B tile buffer
#define STAGES 3
#define GEMM_SMEM_BYTES (STAGES * 2 * SM_BUF * 4)  // 60 KB

__device__ __forceinline__ void cp16(uint32_t dst, const void* src) {
    asm volatile("cp.async.cg.shared.global [%0], [%1], 16;"
                 :: "r"(dst), "l"(src));
}

// one k-step (K=16): k0w = word offset (0 or 8) within the 32-half chunk
__device__ __forceinline__ void mma_ks(const uint32_t* __restrict__ As_,
                                       const uint32_t* __restrict__ Bs_,
                                       float (&acc)[2][8][4],
                                       int k0w, int wm, int wn, int gq, int tq) {
    uint32_t af[2][4], bf[8][2];
#pragma unroll
    for (int mt = 0; mt < 2; mt++) {
        int r = wm + mt * 16 + gq;
        af[mt][0] = As_[r * SMSW + k0w + tq];
        af[mt][1] = As_[(r + 8) * SMSW + k0w + tq];
        af[mt][2] = As_[r * SMSW + k0w + tq + 4];
        af[mt][3] = As_[(r + 8) * SMSW + k0w + tq + 4];
    }
#pragma unroll
    for (int nt = 0; nt < 8; nt++) {
        int n = wn + nt * 8 + gq;
        bf[nt][0] = Bs_[n * SMSW + k0w + tq];
        bf[nt][1] = Bs_[n * SMSW + k0w + tq + 4];
    }
#pragma unroll
    for (int mt = 0; mt < 2; mt++)
#pragma unroll
        for (int nt = 0; nt < 8; nt++) {
            asm volatile(
                "mma.sync.aligned.m16n8k16.row.col.f32.f16.f16.f32 "
                "{%0,%1,%2,%3}, {%4,%5,%6,%7}, {%8,%9}, {%0,%1,%2,%3};"
                : "+f"(acc[mt][nt][0]), "+f"(acc[mt][nt][1]),
                  "+f"(acc[mt][nt][2]), "+f"(acc[mt][nt][3])
                : "r"(af[mt][0]), "r"(af[mt][1]),
                  "r"(af[mt][2]), "r"(af[mt][3]),
                  "r"(bf[nt][0]), "r"(bf[nt][1]));
        }
}

template <int MODE>
__global__ void __launch_bounds__(256, 2)
mma_gemm_kernel() {
    extern __shared__ uint32_t smem[];  // STAGES x [A | B]

    const __half* A  = g_a;
    const __half* Bt = MODE ? g_w2t : g_w1t;

    int tid = threadIdx.x, wid = tid >> 5, lane = tid & 31;
    int row0 = blockIdx.y * 128;
    int col0 = blockIdx.x * 128;
    int wm = (wid & 3) * 32;
    int wn = (wid >> 2) * 64;
    int gq = lane >> 2;
    int tq = lane & 3;

    uint32_t sbase = (uint32_t)__cvta_generic_to_shared(smem);

    // per-thread fixed load slots: 2 x 16B (=8 halfs) for A, 2 for B
    int lr[2], lw[2], lh[2], lgrow[2];
#pragma unroll
    for (int i = 0; i < 2; i++) {
        int idx = tid + 256 * i;          // 0..511
        lr[i] = idx >> 2;                 // row 0..127
        lw[i] = (idx & 3) * 4;            // word offset in row
        lh[i] = (idx & 3) * 8;            // half offset in row
        int grow = row0 + lr[i];
        lgrow[i] = (grow < NNODES) ? grow : (NNODES - 1);  // clamp: rows >= N never stored
    }

    float acc[2][8][4];
#pragma unroll
    for (int mt = 0; mt < 2; mt++)
#pragma unroll
        for (int nt = 0; nt < 8; nt++)
#pragma unroll
            for (int j = 0; j < 4; j++) acc[mt][nt][j] = 0.f;

    // issue one chunk into stage st
    auto issue_chunk = [&](int c, int st) {
        int kh = c * 32;
        uint32_t abuf = sbase + (uint32_t)(st * 2 * SM_BUF) * 4;
        uint32_t bbuf = abuf + SM_BUF * 4;
#pragma unroll
        for (int i = 0; i < 2; i++) {
            cp16(abuf + (uint32_t)(lr[i] * SMSW + lw[i]) * 4,
                 &A[(size_t)lgrow[i] * DIM + kh + lh[i]]);
            cp16(bbuf + (uint32_t)(lr[i] * SMSW + lw[i]) * 4,
                 &Bt[(size_t)(col0 + lr[i]) * DIM + kh + lh[i]]);
        }
        asm volatile("cp.async.commit_group;" ::: "memory");
    };

    // prologue: stages 0,1
    issue_chunk(0, 0);
    issue_chunk(1, 1);

    for (int c = 0; c < 16; c++) {
        // chunk c resident (groups complete in order)
        if (c < 15) asm volatile("cp.async.wait_group 1;" ::: "memory");
        else        asm volatile("cp.async.wait_group 0;" ::: "memory");
        __syncthreads();   // CTA-wide visibility of chunk c; all reads of c-1 done

        if (c + 2 < 16) issue_chunk(c + 2, (c + 2) % STAGES);

        const uint32_t* curA = smem + (c % STAGES) * 2 * SM_BUF;
        const uint32_t* curB = curA + SM_BUF;
        mma_ks(curA, curB, acc, 0, wm, wn, gq, tq);   // K 0..15
        mma_ks(curA, curB, acc, 8, wm, wn, gq, tq);   // K 16..31
    }

    // ---- epilogue: fragments -> g_h (fp16) ----
#pragma unroll
    for (int mt = 0; mt < 2; mt++) {
        int r0 = row0 + wm + mt * 16 + gq;
#pragma unroll
        for (int nt = 0; nt < 8; nt++) {
            int cc = col0 + wn + nt * 8 + tq * 2;
            if (r0 < NNODES)
                *(__half2*)&g_h[(size_t)r0 * DIM + cc] =
                    __floats2half2_rn(acc[mt][nt][0], acc[mt][nt][1]);
            if (r0 + 8 < NNODES)
                *(__half2*)&g_h[(size_t)(r0 + 8) * DIM + cc] =
                    __floats2half2_rn(acc[mt][nt][2], acc[mt][nt][3]);
        }
    }
}

// ---------------------------------------------------------------------------
// Launch 5: dinv + coalesced smem prefix scan of (deg-1) -> rowptr, cursor.
// ---------------------------------------------------------------------------
#define SCAN_T 1024
#define SCAN_CH ((NNODES + SCAN_T - 1) / SCAN_T)   // 20
#define SCAN_SMEM ((NNODES + SCAN_T) * 4)
__global__ void scan_dinv_kernel() {
    extern __shared__ int sm[];
    int* sums = sm + NNODES;
    int t = threadIdx.x;

    for (int i = t; i < NNODES; i += SCAN_T) {
        int dg = g_deg[i];
        g_dinv[i] = rsqrtf((float)dg);
        sm[i] = dg - 1;
    }
    __syncthreads();

    int base = t * SCAN_CH;
    int local = 0;
#pragma unroll
    for (int i = 0; i < SCAN_CH; i++) {
        int idx = base + i;
        if (idx < NNODES) local += sm[idx];
    }
    sums[t] = local;
    __syncthreads();
    for (int o = 1; o < SCAN_T; o <<= 1) {
        int v = (t >= o) ? sums[t - o] : 0;
        __syncthreads();
        sums[t] += v;
        __syncthreads();
    }
    int run = (t > 0) ? sums[t - 1] : 0;
#pragma unroll
    for (int i = 0; i < SCAN_CH; i++) {
        int idx = base + i;
        if (idx < NNODES) {
            int v = sm[idx];
            sm[idx] = run;
            run += v;
        }
    }
    __syncthreads();
    for (int i = t; i < NNODES; i += SCAN_T) {
        int r = sm[i];
        g_rowptr[i] = r;
        g_cursor[i] = r;
    }
    if (t == SCAN_T - 1) g_rowptr[NNODES] = sums[SCAN_T - 1];
}

// ---------------------------------------------------------------------------
// Launch 6: scatter edges into CSR (by dst), precomputing edge weight
// ---------------------------------------------------------------------------
__global__ void scatter_kernel() {
    int e = blockIdx.x * blockDim.x + threadIdx.x;
    if (e >= NEDGES) return;
    int s = g_src[e];
    int d = g_dst[e];
    int pos = atomicAdd(&g_cursor[d], 1);
    g_csr_src[pos] = s;
    g_csr_w[pos] = g_dinv[s] * g_dinv[d];
}

// ---------------------------------------------------------------------------
// Shared edge-accumulate body (fp32 accumulation over fp16 gathers):
//   acc = dinv[d]^2 * h[d,:] + sum_{e: dst=d} w_e * h[src_e,:]
// ---------------------------------------------------------------------------
__device__ __forceinline__ float4 h_load4(const uint2* __restrict__ hp, size_t idx) {
    uint2 raw = hp[idx];
    float2 f0 = __half22float2(*(__half2*)&raw.x);
    float2 f1 = __half22float2(*(__half2*)&raw.y);
    return make_float4(f0.x, f0.y, f1.x, f1.y);
}

__device__ __forceinline__ float4 agg_row(int d, int t) {
    const uint2* __restrict__ hp = (const uint2*)g_h;
    float dv = g_dinv[d];
    float4 acc = h_load4(hp, (size_t)d * 128 + t);
    float ws = dv * dv;
    acc.x *= ws; acc.y *= ws; acc.z *= ws; acc.w *= ws;

    int j   = g_rowptr[d];
    int end = g_rowptr[d + 1];
    for (; j + 4 <= end; j += 4) {
        int   s0 = g_csr_src[j],     s1 = g_csr_src[j + 1];
        int   s2 = g_csr_src[j + 2], s3 = g_csr_src[j + 3];
        float w0 = g_csr_w[j],       w1 = g_csr_w[j + 1];
        float w2 = g_csr_w[j + 2],   w3 = g_csr_w[j + 3];
        float4 v0 = h_load4(hp, (size_t)s0 * 128 + t);
        float4 v1 = h_load4(hp, (size_t)s1 * 128 + t);
        float4 v2 = h_load4(hp, (size_t)s2 * 128 + t);
        float4 v3 = h_load4(hp, (size_t)s3 * 128 + t);
        acc.x += v0.x * w0 + v1.x * w1 + v2.x * w2 + v3.x * w3;
        acc.y += v0.y * w0 + v1.y * w1 + v2.y * w2 + v3.y * w3;
        acc.z += v0.z * w0 + v1.z * w1 + v2.z * w2 + v3.z * w3;
        acc.w += v0.w * w0 + v1.w * w1 + v2.w * w2 + v3.w * w3;
    }
    for (; j < end; j++) {
        int   s = g_csr_src[j];
        float w = g_csr_w[j];
        float4 v = h_load4(hp, (size_t)s * 128 + t);
        acc.x += v.x * w; acc.y += v.y * w;
        acc.z += v.z * w; acc.w += v.w * w;
    }
    return acc;
}

// Layer 1: agg + bias + relu -> fp16 g_a (layer-2 GEMM A operand)
__global__ void __launch_bounds__(128)
agg_csr_half_kernel(const float* __restrict__ b1) {
    int d = blockIdx.x;
    int t = threadIdx.x;
    float4 acc = agg_row(d, t);
    float4 bb = ((const float4*)b1)[t];
    __half2 h0 = __floats2half2_rn(fmaxf(acc.x + bb.x, 0.f), fmaxf(acc.y + bb.y, 0.f));
    __half2 h1 = __floats2half2_rn(fmaxf(acc.z + bb.z, 0.f), fmaxf(acc.w + bb.w, 0.f));
    ((uint2*)g_a)[(size_t)d * 128 + t] = make_uint2(*(uint32_t*)&h0, *(uint32_t*)&h1);
}

// Layer 2: plain fp32 aggregation -> g_agg (consumed by maxpool)
__global__ void __launch_bounds__(128)
agg_csr_kernel() {
    int d = blockIdx.x;
    int t = threadIdx.x;
    ((float4*)g_agg)[(size_t)d * 128 + t] = agg_row(d, t);
}

// ---------------------------------------------------------------------------
// Max pool: out[j] = max_i relu(agg[i,j] + b2[j])  (out pre-zeroed in launch 1)
// ---------------------------------------------------------------------------
#define POOL_ROWS 100
__global__ void maxpool_kernel(const float* __restrict__ b2, float* __restrict__ out) {
    int col  = threadIdx.x;   // 512 threads
    int row0 = blockIdx.x * POOL_ROWS;
    float bb = b2[col];
    float m = 0.f;
#pragma unroll 4
    for (int r = 0; r < POOL_ROWS; r++) {
        int row = row0 + r;
        if (row >= NNODES) break;
        float v = g_agg[(size_t)row * DIM + col] + bb;
        m = fmaxf(m, fmaxf(v, 0.f));
    }
    atomicMax((int*)out + col, __float_as_int(m));
}

// ---------------------------------------------------------------------------
extern "C" void kernel_launch(void* const* d_in, const int* in_sizes, int n_in,
                              void* d_out, int out_size) {
    const float* X  = (const float*)d_in[0];
    const void*  ei = d_in[1];
    // d_in[2] = edge_attr (unused by GCNConv)
    const float* W1 = (const float*)d_in[3];
    const float* b1 = (const float*)d_in[4];
    const float* W2 = (const float*)d_in[5];
    const float* b2 = (const float*)d_in[6];
    float* out = (float*)d_out;

    cudaFuncSetAttribute(scan_dinv_kernel,
                         cudaFuncAttributeMaxDynamicSharedMemorySize, SCAN_SMEM);
    cudaFuncSetAttribute(mma_gemm_kernel<0>,
                         cudaFuncAttributeMaxDynamicSharedMemorySize, GEMM_SMEM_BYTES);
    cudaFuncSetAttribute(mma_gemm_kernel<1>,
                         cudaFuncAttributeMaxDynamicSharedMemorySize, GEMM_SMEM_BYTES);

    dim3 gemm_grid(DIM / 128, (NNODES + 127) / 128);  // (4, 157)

    // 1: deg init | W transpose+fp16 | X->fp16 | out init | flag reset
    init_misc_kernel<<<DEGI_BLKS + TRAN_BLKS + XCNV_BLKS + 1, 256>>>(X, W1, W2, out);
    // 2: dtype sniff
    dtype_sniff_kernel<<<(NEDGES + 255) / 256, 256>>>((const int*)ei);
    // 3: edge convert + degree count
    convert_count_kernel<<<(2 * NEDGES + 255) / 256, 256>>>(ei);
    // 4: layer-1 GEMM (profiled slot)  h = fp16(X) @ W1  (fp32 acc) -> fp16
    mma_gemm_kernel<0><<<gemm_grid, 256, GEMM_SMEM_BYTES>>>();
    // 5: dinv + rowptr scan
    scan_dinv_kernel<<<1, SCAN_T, SCAN_SMEM>>>();
    // 6: CSR scatter
    scatter_kernel<<<(NEDGES + 255) / 256, 256>>>();
    // 7: layer-1 aggregation -> fp16(relu(a + b1))
    agg_csr_half_kernel<<<NNODES, 128>>>(b1);
    // 8: layer-2 GEMM  h = a @ W2 -> fp16
    mma_gemm_kernel<1><<<gemm_grid, 256, GEMM_SMEM_BYTES>>>();
    // 9: layer-2 aggregation (fp32)
    agg_csr_kernel<<<NNODES, 128>>>();
    // 10: global max pool over relu(agg + b2)
    maxpool_kernel<<<(NNODES + POOL_ROWS - 1) / POOL_ROWS, DIM>>>(b2, out);
}

// round 17
// speedup vs baseline: 1.9218x; 1.0896x over previous
#include <cuda_runtime.h>
#include <cuda_fp16.h>
#include <cstdint>

#define NNODES 20000
#define NEDGES 320000
#define DIM    512

// Scratch (allocation-free rule: __device__ globals)
__device__ __half g_h[(size_t)NNODES * DIM];  // GEMM output h (fp16 storage)
__device__ __half g_a[(size_t)NNODES * DIM];  // GEMM A operand (fp16)
__device__ float  g_agg[(size_t)NNODES * DIM]; // layer-2 agg result (fp32)
__device__ float  g_dinv[NNODES];
__device__ int    g_deg[NNODES];
__device__ int    g_src[NEDGES];
__device__ int    g_dst[NEDGES];
__device__ int    g_is_i32;           // nonzero -> edge_index buffer is int32
__device__ int    g_rowptr[NNODES + 1];
__device__ int    g_cursor[NNODES];
__device__ int    g_csr_src[NEDGES];
__device__ float  g_csr_w[NEDGES];
__device__ __half g_w1t[DIM * DIM];   // W1^T, fp16
__device__ __half g_w2t[DIM * DIM];   // W2^T, fp16

// ---------------------------------------------------------------------------
// Launch 1 (fused): deg init | W transpose+fp16 | X->fp16 | out init + flag
// ---------------------------------------------------------------------------
#define DEGI_BLKS 79
#define TRAN_BLKS 512
#define XCNV_BLKS (NNODES * (DIM / 4) / 256)   // 10000
__global__ void init_misc_kernel(const float* __restrict__ X,
                                 const float* __restrict__ W1,
                                 const float* __restrict__ W2,
                                 float* __restrict__ out) {
    int b = blockIdx.x;
    int t = threadIdx.x;
    if (b < DEGI_BLKS) {
        int i = b * 256 + t;
        if (i < NNODES) g_deg[i] = 1;  // self-loop
        return;
    }
    if (b < DEGI_BLKS + TRAN_BLKS) {
        __shared__ float ts[32][33];
        int tile = b - DEGI_BLKS;
        const float* W = (tile >= 256) ? W2 : W1;
        __half* o = (tile >= 256) ? g_w2t : g_w1t;
        int tl = tile & 255;
        int bx = (tl & 15) * 32, by = (tl >> 4) * 32;
        int r = t >> 3, c = (t & 7) * 4;
        float4 v = *(const float4*)&W[(size_t)(by + r) * DIM + bx + c];
        ts[r][c] = v.x; ts[r][c + 1] = v.y; ts[r][c + 2] = v.z; ts[r][c + 3] = v.w;
        __syncthreads();
        __half2 h0 = __floats2half2_rn(ts[c][r], ts[c + 1][r]);
        __half2 h1 = __floats2half2_rn(ts[c + 2][r], ts[c + 3][r]);
        uint2 ov = make_uint2(*(uint32_t*)&h0, *(uint32_t*)&h1);
        *(uint2*)&o[(size_t)(bx + r) * DIM + by + c] = ov;
        return;
    }
    if (b < DEGI_BLKS + TRAN_BLKS + XCNV_BLKS) {
        int idx = (b - DEGI_BLKS - TRAN_BLKS) * 256 + t;
        float4 v = ((const float4*)X)[idx];
        __half2 h0 = __floats2half2_rn(v.x, v.y);
        __half2 h1 = __floats2half2_rn(v.z, v.w);
        ((uint2*)g_a)[idx] = make_uint2(*(uint32_t*)&h0, *(uint32_t*)&h1);
        return;
    }
    out[t] = 0.0f;
    out[t + 256] = 0.0f;
    if (t == 0) g_is_i32 = 0;
}

// ---------------------------------------------------------------------------
// Launch 2: int32 vs int64 sniff (odd words all zero <=> int64)
// ---------------------------------------------------------------------------
__global__ void dtype_sniff_kernel(const int* __restrict__ ei32) {
    int i = blockIdx.x * blockDim.x + threadIdx.x;  // 0 .. E-1
    int acc = 0;
    if (i < NEDGES) acc = ei32[2 * i + 1];
#pragma unroll
    for (int o = 16; o > 0; o >>= 1) acc |= __shfl_xor_sync(0xffffffffu, acc, o);
    if ((threadIdx.x & 31) == 0 && acc != 0) atomicOr(&g_is_i32, 1);
}

// ---------------------------------------------------------------------------
// Launch 3: convert edge index to int32 + count in-degree
// ---------------------------------------------------------------------------
__global__ void convert_count_kernel(const void* __restrict__ ei) {
    int i = blockIdx.x * blockDim.x + threadIdx.x;  // 0 .. 2E-1
    if (i >= 2 * NEDGES) return;
    int v;
    if (g_is_i32) v = ((const int*)ei)[i];
    else          v = (int)((const long long*)ei)[i];
    if (i < NEDGES) {
        g_src[i] = v;
    } else {
        g_dst[i - NEDGES] = v;
        atomicAdd(&g_deg[v], 1);
    }
}

// ---------------------------------------------------------------------------
// Launch 4 (profiled slot): 3-stage cp.async + ldmatrix fp16 HMMA GEMM:
//   g_h[M,512] = g_a[M,512] @ Wt^T (fp16 in, fp32 acc, fp16 out)
// CTA 128x128, BK=32, 256 threads = 8 warps (4 M x 2 N), warp tile 32x64.
// Fragment loads via ldmatrix.x4 (6 LDSM vs 24 LDS per thread per k-step).
// ---------------------------------------------------------------------------
#define SMSW 20                            // smem row stride in words (16 + 4 pad)
#define SM_BUF (128 * SMSW)                // words per A or B tile buffer
#define STAGES 3
#define GEMM_SMEM_BYTES (STAGES * 2 * SM_BUF * 4)  // 60 KB

__device__ __forceinline__ void cp16(uint32_t dst, const void* src) {
    asm volatile("cp.async.cg.shared.global [%0], [%1], 16;"
                 :: "r"(dst), "l"(src));
}

__device__ __forceinline__ void ldsm_x4(uint32_t addr, uint32_t& r0, uint32_t& r1,
                                        uint32_t& r2, uint32_t& r3) {
    asm volatile("ldmatrix.sync.aligned.m8n8.x4.shared.b16 {%0,%1,%2,%3}, [%4];"
                 : "=r"(r0), "=r"(r1), "=r"(r2), "=r"(r3) : "r"(addr));
}

// one k-step (K=16): koff = byte offset of the k-halfword group (0 or 32)
__device__ __forceinline__ void mma_ks(uint32_t aS, uint32_t bS, uint32_t koff,
                                       const uint32_t (&a_off)[2],
                                       const uint32_t (&b_off)[4],
                                       float (&acc)[2][8][4]) {
    uint32_t af[2][4], bf[8][2];
#pragma unroll
    for (int mt = 0; mt < 2; mt++)
        ldsm_x4(aS + a_off[mt] + koff, af[mt][0], af[mt][1], af[mt][2], af[mt][3]);
#pragma unroll
    for (int p = 0; p < 4; p++)
        ldsm_x4(bS + b_off[p] + koff,
                bf[2 * p][0], bf[2 * p][1], bf[2 * p + 1][0], bf[2 * p + 1][1]);
#pragma unroll
    for (int mt = 0; mt < 2; mt++)
#pragma unroll
        for (int nt = 0; nt < 8; nt++) {
            asm volatile(
                "mma.sync.aligned.m16n8k16.row.col.f32.f16.f16.f32 "
                "{%0,%1,%2,%3}, {%4,%5,%6,%7}, {%8,%9}, {%0,%1,%2,%3};"
                : "+f"(acc[mt][nt][0]), "+f"(acc[mt][nt][1]),
                  "+f"(acc[mt][nt][2]), "+f"(acc[mt][nt][3])
                : "r"(af[mt][0]), "r"(af[mt][1]),
                  "r"(af[mt][2]), "r"(af[mt][3]),
                  "r"(bf[nt][0]), "r"(bf[nt][1]));
        }
}

template <int MODE>
__global__ void __launch_bounds__(256, 2)
mma_gemm_kernel() {
    extern __shared__ uint32_t smem[];  // STAGES x [A | B]

    const __half* A  = g_a;
    const __half* Bt = MODE ? g_w2t : g_w1t;

    int tid = threadIdx.x, wid = tid >> 5, lane = tid & 31;
    int row0 = blockIdx.y * 128;
    int col0 = blockIdx.x * 128;
    int wm = (wid & 3) * 32;
    int wn = (wid >> 2) * 64;

    uint32_t sbase = (uint32_t)__cvta_generic_to_shared(smem);

    // ldmatrix per-lane fragment byte offsets (within one stage's A/B buffer)
    // matrix order for A (mt): {rows+0,w+0} {rows+8,w+0} {rows+0,w+4} {rows+8,w+4}
    // matrix order for B (pair p): {nt=2p,w+0} {nt=2p,w+4} {nt=2p+1,w+0} {nt=2p+1,w+4}
    int mj = lane >> 3, rr = lane & 7;
    uint32_t a_off[2], b_off[4];
#pragma unroll
    for (int mt = 0; mt < 2; mt++)
        a_off[mt] = (uint32_t)(((wm + mt * 16 + (mj & 1) * 8 + rr) * SMSW
                                + (mj >> 1) * 4) * 4);
#pragma unroll
    for (int p = 0; p < 4; p++)
        b_off[p] = (uint32_t)(((wn + (2 * p + (mj >> 1)) * 8 + rr) * SMSW
                               + (mj & 1) * 4) * 4);

    // per-thread fixed load slots: 2 x 16B (=8 halfs) for A, 2 for B
    int lr[2], lw[2], lh[2], lgrow[2];
#pragma unroll
    for (int i = 0; i < 2; i++) {
        int idx = tid + 256 * i;          // 0..511
        lr[i] = idx >> 2;                 // row 0..127
        lw[i] = (idx & 3) * 4;            // word offset in row
        lh[i] = (idx & 3) * 8;            // half offset in row
        int grow = row0 + lr[i];
        lgrow[i] = (grow < NNODES) ? grow : (NNODES - 1);  // clamp: rows >= N never stored
    }

    float acc[2][8][4];
#pragma unroll
    for (int mt = 0; mt < 2; mt++)
#pragma unroll
        for (int nt = 0; nt < 8; nt++)
#pragma unroll
            for (int j = 0; j < 4; j++) acc[mt][nt][j] = 0.f;

    auto issue_chunk = [&](int c, int st) {
        int kh = c * 32;
        uint32_t abuf = sbase + (uint32_t)(st * 2 * SM_BUF) * 4;
        uint32_t bbuf = abuf + SM_BUF * 4;
#pragma unroll
        for (int i = 0; i < 2; i++) {
            cp16(abuf + (uint32_t)(lr[i] * SMSW + lw[i]) * 4,
                 &A[(size_t)lgrow[i] * DIM + kh + lh[i]]);
            cp16(bbuf + (uint32_t)(lr[i] * SMSW + lw[i]) * 4,
                 &Bt[(size_t)(col0 + lr[i]) * DIM + kh + lh[i]]);
        }
        asm volatile("cp.async.commit_group;" ::: "memory");
    };

    // prologue: stages 0,1
    issue_chunk(0, 0);
    issue_chunk(1, 1);

    for (int c = 0; c < 16; c++) {
        if (c < 15) asm volatile("cp.async.wait_group 1;" ::: "memory");
        else        asm volatile("cp.async.wait_group 0;" ::: "memory");
        __syncthreads();   // chunk c visible; all reads of c-1 done

        if (c + 2 < 16) issue_chunk(c + 2, (c + 2) % STAGES);

        uint32_t aS = sbase + (uint32_t)((c % STAGES) * 2 * SM_BUF) * 4;
        uint32_t bS = aS + SM_BUF * 4;
        mma_ks(aS, bS, 0,  a_off, b_off, acc);   // K 0..15
        mma_ks(aS, bS, 32, a_off, b_off, acc);   // K 16..31
    }

    // ---- epilogue: fragments -> g_h (fp16) ----
    int gq = lane >> 2, tq = lane & 3;
#pragma unroll
    for (int mt = 0; mt < 2; mt++) {
        int r0 = row0 + wm + mt * 16 + gq;
#pragma unroll
        for (int nt = 0; nt < 8; nt++) {
            int cc = col0 + wn + nt * 8 + tq * 2;
            if (r0 < NNODES)
                *(__half2*)&g_h[(size_t)r0 * DIM + cc] =
                    __floats2half2_rn(acc[mt][nt][0], acc[mt][nt][1]);
            if (r0 + 8 < NNODES)
                *(__half2*)&g_h[(size_t)(r0 + 8) * DIM + cc] =
                    __floats2half2_rn(acc[mt][nt][2], acc[mt][nt][3]);
        }
    }
}

// ---------------------------------------------------------------------------
// Launch 5: dinv + coalesced smem prefix scan of (deg-1) -> rowptr, cursor.
// ---------------------------------------------------------------------------
#define SCAN_T 1024
#define SCAN_CH ((NNODES + SCAN_T - 1) / SCAN_T)   // 20
#define SCAN_SMEM ((NNODES + SCAN_T) * 4)
__global__ void scan_dinv_kernel() {
    extern __shared__ int sm[];
    int* sums = sm + NNODES;
    int t = threadIdx.x;

    for (int i = t; i < NNODES; i += SCAN_T) {
        int dg = g_deg[i];
        g_dinv[i] = rsqrtf((float)dg);
        sm[i] = dg - 1;
    }
    __syncthreads();

    int base = t * SCAN_CH;
    int local = 0;
#pragma unroll
    for (int i = 0; i < SCAN_CH; i++) {
        int idx = base + i;
        if (idx < NNODES) local += sm[idx];
    }
    sums[t] = local;
    __syncthreads();
    for (int o = 1; o < SCAN_T; o <<= 1) {
        int v = (t >= o) ? sums[t - o] : 0;
        __syncthreads();
        sums[t] += v;
        __syncthreads();
    }
    int run = (t > 0) ? sums[t - 1] : 0;
#pragma unroll
    for (int i = 0; i < SCAN_CH; i++) {
        int idx = base + i;
        if (idx < NNODES) {
            int v = sm[idx];
            sm[idx] = run;
            run += v;
        }
    }
    __syncthreads();
    for (int i = t; i < NNODES; i += SCAN_T) {
        int r = sm[i];
        g_rowptr[i] = r;
        g_cursor[i] = r;
    }
    if (t == SCAN_T - 1) g_rowptr[NNODES] = sums[SCAN_T - 1];
}

// ---------------------------------------------------------------------------
// Launch 6: scatter edges into CSR (by dst), precomputing edge weight
// ---------------------------------------------------------------------------
__global__ void scatter_kernel() {
    int e = blockIdx.x * blockDim.x + threadIdx.x;
    if (e >= NEDGES) return;
    int s = g_src[e];
    int d = g_dst[e];
    int pos = atomicAdd(&g_cursor[d], 1);
    g_csr_src[pos] = s;
    g_csr_w[pos] = g_dinv[s] * g_dinv[d];
}

// ---------------------------------------------------------------------------
// Shared edge-accumulate body (fp32 accumulation over fp16 gathers):
//   acc = dinv[d]^2 * h[d,:] + sum_{e: dst=d} w_e * h[src_e,:]
// ---------------------------------------------------------------------------
__device__ __forceinline__ float4 h_load4(const uint2* __restrict__ hp, size_t idx) {
    uint2 raw = hp[idx];
    float2 f0 = __half22float2(*(__half2*)&raw.x);
    float2 f1 = __half22float2(*(__half2*)&raw.y);
    return make_float4(f0.x, f0.y, f1.x, f1.y);
}

__device__ __forceinline__ float4 agg_row(int d, int t) {
    const uint2* __restrict__ hp = (const uint2*)g_h;
    float dv = g_dinv[d];
    float4 acc = h_load4(hp, (size_t)d * 128 + t);
    float ws = dv * dv;
    acc.x *= ws; acc.y *= ws; acc.z *= ws; acc.w *= ws;

    int j   = g_rowptr[d];
    int end = g_rowptr[d + 1];
    for (; j + 4 <= end; j += 4) {
        int   s0 = g_csr_src[j],     s1 = g_csr_src[j + 1];
        int   s2 = g_csr_src[j + 2], s3 = g_csr_src[j + 3];
        float w0 = g_csr_w[j],       w1 = g_csr_w[j + 1];
        float w2 = g_csr_w[j + 2],   w3 = g_csr_w[j + 3];
        float4 v0 = h_load4(hp, (size_t)s0 * 128 + t);
        float4 v1 = h_load4(hp, (size_t)s1 * 128 + t);
        float4 v2 = h_load4(hp, (size_t)s2 * 128 + t);
        float4 v3 = h_load4(hp, (size_t)s3 * 128 + t);
        acc.x += v0.x * w0 + v1.x * w1 + v2.x * w2 + v3.x * w3;
        acc.y += v0.y * w0 + v1.y * w1 + v2.y * w2 + v3.y * w3;
        acc.z += v0.z * w0 + v1.z * w1 + v2.z * w2 + v3.z * w3;
        acc.w += v0.w * w0 + v1.w * w1 + v2.w * w2 + v3.w * w3;
    }
    for (; j < end; j++) {
        int   s = g_csr_src[j];
        float w = g_csr_w[j];
        float4 v = h_load4(hp, (size_t)s * 128 + t);
        acc.x += v.x * w; acc.y += v.y * w;
        acc.z += v.z * w; acc.w += v.w * w;
    }
    return acc;
}

// Layer 1: agg + bias + relu -> fp16 g_a (layer-2 GEMM A operand)
__global__ void __launch_bounds__(128)
agg_csr_half_kernel(const float* __restrict__ b1) {
    int d = blockIdx.x;
    int t = threadIdx.x;
    float4 acc = agg_row(d, t);
    float4 bb = ((const float4*)b1)[t];
    __half2 h0 = __floats2half2_rn(fmaxf(acc.x + bb.x, 0.f), fmaxf(acc.y + bb.y, 0.f));
    __half2 h1 = __floats2half2_rn(fmaxf(acc.z + bb.z, 0.f), fmaxf(acc.w + bb.w, 0.f));
    ((uint2*)g_a)[(size_t)d * 128 + t] = make_uint2(*(uint32_t*)&h0, *(uint32_t*)&h1);
}

// Layer 2: plain fp32 aggregation -> g_agg (consumed by maxpool)
__global__ void __launch_bounds__(128)
agg_csr_kernel() {
    int d = blockIdx.x;
    int t = threadIdx.x;
    ((float4*)g_agg)[(size_t)d * 128 + t] = agg_row(d, t);
}

// ---------------------------------------------------------------------------
// Max pool: out[j] = max_i relu(agg[i,j] + b2[j])  (out pre-zeroed in launch 1)
// ---------------------------------------------------------------------------
#define POOL_ROWS 100
__global__ void maxpool_kernel(const float* __restrict__ b2, float* __restrict__ out) {
    int col  = threadIdx.x;   // 512 threads
    int row0 = blockIdx.x * POOL_ROWS;
    float bb = b2[col];
    float m = 0.f;
#pragma unroll 4
    for (int r = 0; r < POOL_ROWS; r++) {
        int row = row0 + r;
        if (row >= NNODES) break;
        float v = g_agg[(size_t)row * DIM + col] + bb;
        m = fmaxf(m, fmaxf(v, 0.f));
    }
    atomicMax((int*)out + col, __float_as_int(m));
}

// ---------------------------------------------------------------------------
extern "C" void kernel_launch(void* const* d_in, const int* in_sizes, int n_in,
                              void* d_out, int out_size) {
    const float* X  = (const float*)d_in[0];
    const void*  ei = d_in[1];
    // d_in[2] = edge_attr (unused by GCNConv)
    const float* W1 = (const float*)d_in[3];
    const float* b1 = (const float*)d_in[4];
    const float* W2 = (const float*)d_in[5];
    const float* b2 = (const float*)d_in[6];
    float* out = (float*)d_out;

    cudaFuncSetAttribute(scan_dinv_kernel,
                         cudaFuncAttributeMaxDynamicSharedMemorySize, SCAN_SMEM);
    cudaFuncSetAttribute(mma_gemm_kernel<0>,
                         cudaFuncAttributeMaxDynamicSharedMemorySize, GEMM_SMEM_BYTES);
    cudaFuncSetAttribute(mma_gemm_kernel<1>,
                         cudaFuncAttributeMaxDynamicSharedMemorySize, GEMM_SMEM_BYTES);

    dim3 gemm_grid(DIM / 128, (NNODES + 127) / 128);  // (4, 157)

    // 1: deg init | W transpose+fp16 | X->fp16 | out init | flag reset
    init_misc_kernel<<<DEGI_BLKS + TRAN_BLKS + XCNV_BLKS + 1, 256>>>(X, W1, W2, out);
    // 2: dtype sniff
    dtype_sniff_kernel<<<(NEDGES + 255) / 256, 256>>>((const int*)ei);
    // 3: edge convert + degree count
    convert_count_kernel<<<(2 * NEDGES + 255) / 256, 256>>>(ei);
    // 4: layer-1 GEMM (profiled slot)  h = fp16(X) @ W1  (fp32 acc) -> fp16
    mma_gemm_kernel<0><<<gemm_grid, 256, GEMM_SMEM_BYTES>>>();
    // 5: dinv + rowptr scan
    scan_dinv_kernel<<<1, SCAN_T, SCAN_SMEM>>>();
    // 6: CSR scatter
    scatter_kernel<<<(NEDGES + 255) / 256, 256>>>();
    // 7: layer-1 aggregation -> fp16(relu(a + b1))
    agg_csr_half_kernel<<<NNODES, 128>>>(b1);
    // 8: layer-2 GEMM  h = a @ W2 -> fp16
    mma_gemm_kernel<1><<<gemm_grid, 256, GEMM_SMEM_BYTES>>>();
    // 9: layer-2 aggregation (fp32)
    agg_csr_kernel<<<NNODES, 128>>>();
    // 10: global max pool over relu(agg + b2)
    maxpool_kernel<<<(NNODES + POOL_ROWS - 1) / POOL_ROWS, DIM>>>(b2, out);
}